// round 7
// baseline (speedup 1.0000x reference)
#include <cuda_runtime.h>
#include <cstdint>
#include <math.h>

#define CC 8192
#define DD 512
#define BM 128
#define BN 128
#define BK 16
#define TM 8
#define TN 8
#define NSPLIT 2
#define NT_PER_SPLIT ((CC / BN) / NSPLIT)   // 32

typedef unsigned long long ull;

// ---- scratch (static __device__, no allocations) ----
__device__ float g_rnorm[CC];
__device__ float g_GT[DD * CC];             // 16 MB: GT[k][row] = G[row][k] (normalized)
__device__ float g_maxv[NSPLIT][CC];
__device__ int   g_am[NSPLIT][CC];
__device__ float g_minv[NSPLIT][CC];
__device__ int   g_an[NSPLIT][CC];
__device__ float g_esum[NSPLIT][CC];
__device__ float g_terms[CC];

// packed f32x2 FMA: d.lo += a.lo*b.lo ; d.hi += a.hi*b.hi  (one issue slot)
__device__ __forceinline__ void fma2(ull& d, ull a, ull b) {
    asm("fma.rn.f32x2 %0, %1, %2, %3;" : "=l"(d) : "l"(a), "l"(b), "l"(d));
}

// ------------------------------------------------------------------
// 1) per-row reciprocal L2 norm
// ------------------------------------------------------------------
__global__ void norms_kernel(const float* __restrict__ x) {
    int row = blockIdx.x;
    float4 v = ((const float4*)(x + row * DD))[threadIdx.x];   // 128 threads * 4 = 512
    float s = v.x * v.x + v.y * v.y + v.z * v.z + v.w * v.w;
    #pragma unroll
    for (int o = 16; o > 0; o >>= 1) s += __shfl_xor_sync(0xffffffffu, s, o);
    __shared__ float sh[4];
    int lane = threadIdx.x & 31, warp = threadIdx.x >> 5;
    if (lane == 0) sh[warp] = s;
    __syncthreads();
    if (threadIdx.x == 0)
        g_rnorm[row] = rsqrtf(sh[0] + sh[1] + sh[2] + sh[3]);
}

// ------------------------------------------------------------------
// 2) transpose + scale: GT[k][row] = x[row][k] * rnorm[row]
// ------------------------------------------------------------------
__global__ void transpose_kernel(const float* __restrict__ x) {
    __shared__ float tile[32][33];
    int kBase = blockIdx.x * 32;
    int rBase = blockIdx.y * 32;
    #pragma unroll
    for (int i = threadIdx.y; i < 32; i += 8) {
        int row = rBase + i;
        tile[i][threadIdx.x] = x[row * DD + kBase + threadIdx.x] * g_rnorm[row];
    }
    __syncthreads();
    #pragma unroll
    for (int i = threadIdx.y; i < 32; i += 8) {
        g_GT[(kBase + i) * CC + rBase + threadIdx.x] = tile[threadIdx.x][i];
    }
}

// ------------------------------------------------------------------
// 3) fused S = G G^T + per-row off-diag {max,argmax,min,argmin,sum exp}
//    f32x2 packed-FMA microkernel. A duplicated in smem, B paired.
// ------------------------------------------------------------------
__global__ void __launch_bounds__(256) simstat_kernel() {
    __shared__ float As2[BK][2 * BM];   // 16 KB, each A value stored twice
    __shared__ float Bs[BK][BN];        // 8 KB

    const int rowBase = blockIdx.x * BM;
    const int split   = blockIdx.y;
    const int tid = threadIdx.x;
    const int tx = tid & 15;            // column group (TN=8 cols)
    const int ty = tid >> 4;            // row group    (TM=8 rows)

    float maxv[TM], minv[TM], esum[TM];
    int   am[TM], an[TM];
    #pragma unroll
    for (int i = 0; i < TM; i++) {
        maxv[i] = -2.0f; minv[i] = 2.0f; esum[i] = 0.0f; am[i] = 0; an[i] = 0;
    }

    for (int nt = 0; nt < NT_PER_SPLIT; nt++) {
        const int colBase = (split * NT_PER_SPLIT + nt) * BN;

        ull acc2[TM][TN / 2];           // 32 packed pairs = 64 fp32 accumulators
        #pragma unroll
        for (int i = 0; i < TM; i++)
            #pragma unroll
            for (int j = 0; j < TN / 2; j++) acc2[i][j] = 0ull;

        for (int k0 = 0; k0 < DD; k0 += BK) {
            // load tiles from GT (coalesced); A stored duplicated
            #pragma unroll
            for (int v = 0; v < 2; v++) {
                int e    = tid + v * 256;        // 0..511
                int kk   = e >> 5;               // k row
                int seg4 = (e & 31) << 2;        // float offset, x4
                float4 a = *(const float4*)&g_GT[(k0 + kk) * CC + rowBase + seg4];
                float4 d0 = make_float4(a.x, a.x, a.y, a.y);
                float4 d1 = make_float4(a.z, a.z, a.w, a.w);
                *(float4*)&As2[kk][seg4 * 2]     = d0;
                *(float4*)&As2[kk][seg4 * 2 + 4] = d1;
                *(float4*)&Bs[kk][seg4] =
                    *(const float4*)&g_GT[(k0 + kk) * CC + colBase + seg4];
            }
            __syncthreads();

            #pragma unroll
            for (int kk = 0; kk < BK; kk++) {
                ull a2[TM], b2[TN / 2];
                // A: duplicated pairs, broadcast across the warp (2 distinct ty)
                const ull* ap = (const ull*)&As2[kk][ty * (2 * TM)];
                #pragma unroll
                for (int i = 0; i < TM; i++) a2[i] = ap[i];
                // B: natural adjacent pairs
                const ull* bp = (const ull*)&Bs[kk][tx * TN];
                #pragma unroll
                for (int j = 0; j < TN / 2; j++) b2[j] = bp[j];
                #pragma unroll
                for (int i = 0; i < TM; i++)
                    #pragma unroll
                    for (int j = 0; j < TN / 2; j++)
                        fma2(acc2[i][j], a2[i], b2[j]);
            }
            __syncthreads();
        }

        // epilogue: fold this 128x128 tile into the running row stats
        #pragma unroll
        for (int i = 0; i < TM; i++) {
            int grow = rowBase + ty * TM + i;
            #pragma unroll
            for (int j = 0; j < TN / 2; j++) {
                #pragma unroll
                for (int h = 0; h < 2; h++) {
                    int gcol = colBase + tx * TN + 2 * j + h;
                    uint32_t bits = h == 0 ? (uint32_t)acc2[i][j]
                                           : (uint32_t)(acc2[i][j] >> 32);
                    float v = __uint_as_float(bits);
                    if (gcol != grow) {
                        esum[i] += __expf(v);
                        if (v > maxv[i]) { maxv[i] = v; am[i] = gcol; }
                        if (v < minv[i]) { minv[i] = v; an[i] = gcol; }
                    }
                }
            }
        }
    }

    // combine across the 16 tx lanes (butterfly within 16-lane subgroups)
    #pragma unroll
    for (int i = 0; i < TM; i++) {
        #pragma unroll
        for (int o = 1; o < 16; o <<= 1) {
            float vm = __shfl_xor_sync(0xffffffffu, maxv[i], o);
            int   im = __shfl_xor_sync(0xffffffffu, am[i],  o);
            if (vm > maxv[i] || (vm == maxv[i] && im < am[i])) { maxv[i] = vm; am[i] = im; }
            float vn = __shfl_xor_sync(0xffffffffu, minv[i], o);
            int   jn = __shfl_xor_sync(0xffffffffu, an[i],  o);
            if (vn < minv[i] || (vn == minv[i] && jn < an[i])) { minv[i] = vn; an[i] = jn; }
            esum[i] += __shfl_xor_sync(0xffffffffu, esum[i], o);
        }
    }
    if (tx == 0) {
        #pragma unroll
        for (int i = 0; i < TM; i++) {
            int grow = rowBase + ty * TM + i;
            g_maxv[split][grow] = maxv[i];
            g_am[split][grow]   = am[i];
            g_minv[split][grow] = minv[i];
            g_an[split][grow]   = an[i];
            g_esum[split][grow] = esum[i];
        }
    }
}

// ------------------------------------------------------------------
// 4) combine splits, margin, w-distances, per-row loss term
// ------------------------------------------------------------------
__global__ void finalize_kernel(const float* __restrict__ w) {
    const int row = blockIdx.x;
    float m = -2.0f, mn = 2.0f, E = 0.0f;
    int ms = 0, ls = 0;
    #pragma unroll
    for (int s = 0; s < NSPLIT; s++) {
        float v = g_maxv[s][row]; int iv = g_am[s][row];
        if (v > m || (v == m && iv < ms)) { m = v; ms = iv; }
        float u = g_minv[s][row]; int ju = g_an[s][row];
        if (u < mn || (u == mn && ju < ls)) { mn = u; ls = ju; }
        E += g_esum[s][row];
    }
    float margin = (1.0f - expf(mn - m)) * expf(m) / E;

    int t = threadIdx.x;                           // 128 threads * float4 = 512
    float4 a = *(const float4*)&w[row * DD + t * 4];
    float4 b = *(const float4*)&w[ms  * DD + t * 4];
    float4 c = *(const float4*)&w[ls  * DD + t * 4];
    float dm = (a.x-b.x)*(a.x-b.x) + (a.y-b.y)*(a.y-b.y)
             + (a.z-b.z)*(a.z-b.z) + (a.w-b.w)*(a.w-b.w);
    float dl = (a.x-c.x)*(a.x-c.x) + (a.y-c.y)*(a.y-c.y)
             + (a.z-c.z)*(a.z-c.z) + (a.w-c.w)*(a.w-c.w);
    #pragma unroll
    for (int o = 16; o > 0; o >>= 1) {
        dm += __shfl_xor_sync(0xffffffffu, dm, o);
        dl += __shfl_xor_sync(0xffffffffu, dl, o);
    }
    __shared__ float sdm[4], sdl[4];
    int lane = t & 31, warp = t >> 5;
    if (lane == 0) { sdm[warp] = dm; sdl[warp] = dl; }
    __syncthreads();
    if (t == 0) {
        float DM = sdm[0] + sdm[1] + sdm[2] + sdm[3];
        float DL = sdl[0] + sdl[1] + sdl[2] + sdl[3];
        g_terms[row] = fmaxf(0.0f, sqrtf(DM) - sqrtf(DL) + margin);
    }
}

// ------------------------------------------------------------------
// 5) deterministic mean
// ------------------------------------------------------------------
__global__ void reduce_kernel(float* __restrict__ out) {
    __shared__ float sh[256];
    int t = threadIdx.x;
    float s = 0.0f;
    for (int i = t; i < CC; i += 256) s += g_terms[i];
    sh[t] = s;
    __syncthreads();
    for (int o = 128; o > 0; o >>= 1) {
        if (t < o) sh[t] += sh[t + o];
        __syncthreads();
    }
    if (t == 0) out[0] = sh[0] / (float)CC;
}

// ------------------------------------------------------------------
extern "C" void kernel_launch(void* const* d_in, const int* in_sizes, int n_in,
                              void* d_out, int out_size) {
    (void)in_sizes; (void)n_in; (void)out_size;
    const float* gt = (const float*)d_in[0];
    const float* w  = (const float*)d_in[1];
    float* out = (float*)d_out;

    norms_kernel<<<CC, 128>>>(gt);
    transpose_kernel<<<dim3(DD / 32, CC / 32), dim3(32, 8)>>>(gt);
    simstat_kernel<<<dim3(CC / BM, NSPLIT), 256>>>();
    finalize_kernel<<<CC, 128>>>(w);
    reduce_kernel<<<1, 256>>>(out);
}

// round 8
// speedup vs baseline: 2.5908x; 2.5908x over previous
#include <cuda_runtime.h>
#include <cuda_bf16.h>
#include <cstdint>
#include <math.h>

#define CC 8192
#define DD 512
#define BM 128
#define BN 128
#define BK 32
#define NCH (DD / BK)            // 16 k-chunks per tile
#define NSPLIT 2
#define NT ((CC / BN) / NSPLIT)  // 32 col tiles per block
#define NITER (NT * NCH)         // 512

#define RSB 80                   // smem row stride bytes (64B data + 16B pad, LDSM conflict-free)
#define MATB (128 * RSB)         // 10240 B per matrix
#define STAGEB (4 * MATB)        // Ahi, Alo, Bhi, Blo
#define SMEMB (2 * STAGEB)       // 81920 B, double buffered

// ---- scratch ----
__device__ __nv_bfloat16 g_hi[CC * DD];
__device__ __nv_bfloat16 g_lo[CC * DD];
__device__ float g_maxv[NSPLIT][CC];
__device__ int   g_am[NSPLIT][CC];
__device__ float g_minv[NSPLIT][CC];
__device__ int   g_an[NSPLIT][CC];
__device__ float g_esum[NSPLIT][CC];
__device__ float g_terms[CC];

// ================= helpers =================
__device__ __forceinline__ uint32_t smem_to_u32(const void* p) {
    uint32_t a;
    asm("{ .reg .u64 t; cvta.to.shared.u64 t, %1; cvt.u32.u64 %0, t; }" : "=r"(a) : "l"(p));
    return a;
}
#define CP_ASYNC16(dst, src) \
    asm volatile("cp.async.cg.shared.global [%0], [%1], 16;" :: "r"(dst), "l"(src))
#define CP_COMMIT() asm volatile("cp.async.commit_group;" ::: "memory")
#define CP_WAIT1() asm volatile("cp.async.wait_group 1;" ::: "memory")
#define CP_WAIT0() asm volatile("cp.async.wait_group 0;" ::: "memory")

#define LDSM4(d, addr) \
    asm volatile("ldmatrix.sync.aligned.m8n8.x4.shared.b16 {%0,%1,%2,%3}, [%4];" \
        : "=r"((d)[0]), "=r"((d)[1]), "=r"((d)[2]), "=r"((d)[3]) : "r"(addr))

#define MMA_BF16(cr, a, b0, b1) \
    asm volatile("mma.sync.aligned.m16n8k16.row.col.f32.bf16.bf16.f32 " \
        "{%0,%1,%2,%3}, {%4,%5,%6,%7}, {%8,%9}, {%0,%1,%2,%3};" \
        : "+f"((cr)[0]), "+f"((cr)[1]), "+f"((cr)[2]), "+f"((cr)[3]) \
        : "r"((a)[0]), "r"((a)[1]), "r"((a)[2]), "r"((a)[3]), "r"(b0), "r"(b1))

// ------------------------------------------------------------------
// 1) normalize + bf16 hi/lo split, row-major
// ------------------------------------------------------------------
__global__ void transform_kernel(const float* __restrict__ x) {
    int row = blockIdx.x, t = threadIdx.x;
    float4 v = ((const float4*)(x + row * DD))[t];
    float s = v.x * v.x + v.y * v.y + v.z * v.z + v.w * v.w;
    #pragma unroll
    for (int o = 16; o > 0; o >>= 1) s += __shfl_xor_sync(0xffffffffu, s, o);
    __shared__ float sh[4];
    __shared__ float tot;
    int lane = t & 31, warp = t >> 5;
    if (lane == 0) sh[warp] = s;
    __syncthreads();
    if (t == 0) tot = sh[0] + sh[1] + sh[2] + sh[3];
    __syncthreads();
    float rn = rsqrtf(tot);
    float gv[4] = {v.x * rn, v.y * rn, v.z * rn, v.w * rn};
    __nv_bfloat16 hi[4], lo[4];
    #pragma unroll
    for (int i = 0; i < 4; i++) {
        hi[i] = __float2bfloat16(gv[i]);
        lo[i] = __float2bfloat16(gv[i] - __bfloat162float(hi[i]));
    }
    __nv_bfloat162* ph = (__nv_bfloat162*)g_hi + row * (DD / 2) + t * 2;
    __nv_bfloat162* pl = (__nv_bfloat162*)g_lo + row * (DD / 2) + t * 2;
    ph[0] = __halves2bfloat162(hi[0], hi[1]);
    ph[1] = __halves2bfloat162(hi[2], hi[3]);
    pl[0] = __halves2bfloat162(lo[0], lo[1]);
    pl[1] = __halves2bfloat162(lo[2], lo[3]);
}

// ------------------------------------------------------------------
// 2) bf16x3 mma.sync GEMM + fused row stats
//    grid (64, NSPLIT), 256 threads = 8 warps (4 m x 2 n), warp tile 32x64
// ------------------------------------------------------------------
__device__ __forceinline__ void prefetch_stage(uint32_t sb, int tid, int rowBase,
                                               int split, int it) {
    const int tile = it >> 4, chunk = it & 15;
    const uint32_t st = sb + (uint32_t)(it & 1) * STAGEB;
    const int colBase = (split * NT + tile) * BN;
    const int kb = chunk * BK;
    #pragma unroll
    for (int i = 0; i < 2; ++i) {
        int e = tid + i * 256;          // 0..511
        int r = e >> 2, c4 = e & 3;
        uint32_t doff = (uint32_t)(r * RSB + c4 * 16);
        size_t aoff = (size_t)(rowBase + r) * DD + kb + c4 * 8;
        size_t boff = (size_t)(colBase + r) * DD + kb + c4 * 8;
        CP_ASYNC16(st + 0 * MATB + doff, g_hi + aoff);
        CP_ASYNC16(st + 1 * MATB + doff, g_lo + aoff);
        CP_ASYNC16(st + 2 * MATB + doff, g_hi + boff);
        CP_ASYNC16(st + 3 * MATB + doff, g_lo + boff);
    }
    CP_COMMIT();
}

__global__ void __launch_bounds__(256, 1) simstat_mma() {
    extern __shared__ char smem[];
    const uint32_t sb = smem_to_u32(smem);
    const int tid = threadIdx.x;
    const int lane = tid & 31, wid = tid >> 5;
    const int warp_m = wid >> 1, warp_n = wid & 1;
    const int rowBase = blockIdx.x * BM;
    const int split = blockIdx.y;
    const int g = lane >> 2, tg = lane & 3;

    float maxv[4], minv[4], esum[4];
    int am[4], an[4];
    #pragma unroll
    for (int s = 0; s < 4; ++s) {
        maxv[s] = -2.0f; minv[s] = 2.0f; esum[s] = 0.0f; am[s] = 0; an[s] = 0;
    }

    // lane-dependent smem byte offsets (ldmatrix, non-trans, 4 8x8 matrices)
    // A: lane L -> row (L&15), col halfsel ((L>>4)&1)*8 bf16
    const uint32_t aoffL = (uint32_t)((lane & 15) * RSB + ((lane >> 4) & 1) * 16)
                         + (uint32_t)(warp_m * 32 * RSB);
    // B: lane L -> n = ((L>>4)&1)*8 + (L&7), col halfsel ((L>>3)&1)*8 bf16
    const uint32_t boffL = (uint32_t)((((lane >> 4) & 1) * 8 + (lane & 7)) * RSB
                         + ((lane >> 3) & 1) * 16)
                         + (uint32_t)(warp_n * 64 * RSB);

    float c[2][8][4];
    int it = 0;
    prefetch_stage(sb, tid, rowBase, split, 0);

    for (int tile = 0; tile < NT; ++tile) {
        const int colBase = (split * NT + tile) * BN;
        #pragma unroll
        for (int mi = 0; mi < 2; ++mi)
            #pragma unroll
            for (int nj = 0; nj < 8; ++nj)
                #pragma unroll
                for (int q = 0; q < 4; ++q) c[mi][nj][q] = 0.0f;

        for (int chunk = 0; chunk < NCH; ++chunk, ++it) {
            __syncthreads();   // everyone done reading buffer (it+1)&1 from it-1
            if (it + 1 < NITER) { prefetch_stage(sb, tid, rowBase, split, it + 1); CP_WAIT1(); }
            else CP_WAIT0();
            __syncthreads();   // stage (it&1) fully resident for all threads

            const uint32_t st = sb + (uint32_t)(it & 1) * STAGEB;
            #pragma unroll
            for (int koi = 0; koi < 2; ++koi) {
                const uint32_t kob = (uint32_t)koi * 32;   // 16 bf16 = 32 B
                uint32_t ah[2][4], al[2][4];
                LDSM4(ah[0], st + 0 * MATB + aoffL + kob);
                LDSM4(ah[1], st + 0 * MATB + aoffL + 16 * RSB + kob);
                LDSM4(al[0], st + 1 * MATB + aoffL + kob);
                LDSM4(al[1], st + 1 * MATB + aoffL + 16 * RSB + kob);
                uint32_t bh[4][4], bl[4][4];
                #pragma unroll
                for (int njp = 0; njp < 4; ++njp) {
                    LDSM4(bh[njp], st + 2 * MATB + boffL + (uint32_t)(njp * 16 * RSB) + kob);
                    LDSM4(bl[njp], st + 3 * MATB + boffL + (uint32_t)(njp * 16 * RSB) + kob);
                }
                #pragma unroll
                for (int mi = 0; mi < 2; ++mi)
                    #pragma unroll
                    for (int nj = 0; nj < 8; ++nj) {
                        uint32_t h0 = bh[nj >> 1][(nj & 1) * 2];
                        uint32_t h1 = bh[nj >> 1][(nj & 1) * 2 + 1];
                        uint32_t l0 = bl[nj >> 1][(nj & 1) * 2];
                        uint32_t l1 = bl[nj >> 1][(nj & 1) * 2 + 1];
                        MMA_BF16(c[mi][nj], ah[mi], h0, h1);
                        MMA_BF16(c[mi][nj], ah[mi], l0, l1);
                        MMA_BF16(c[mi][nj], al[mi], h0, h1);
                    }
            }
        }

        // epilogue: fold tile into running row stats
        #pragma unroll
        for (int mi = 0; mi < 2; ++mi) {
            const int r0 = rowBase + warp_m * 32 + mi * 16 + g;
            const int r1 = r0 + 8;
            const int s0 = mi * 2, s1 = mi * 2 + 1;
            #pragma unroll
            for (int nj = 0; nj < 8; ++nj) {
                const int cb = colBase + warp_n * 64 + nj * 8 + tg * 2;
                #pragma unroll
                for (int q = 0; q < 4; ++q) {
                    const int col = cb + (q & 1);
                    const int slot = (q < 2) ? s0 : s1;
                    const int grow = (q < 2) ? r0 : r1;
                    float v = c[mi][nj][q];
                    if (col != grow) {
                        esum[slot] += __expf(v);
                        if (v > maxv[slot]) { maxv[slot] = v; am[slot] = col; }
                        if (v < minv[slot]) { minv[slot] = v; an[slot] = col; }
                    }
                }
            }
        }
    }

    // reduce across the 4 lanes of each quad (tg)
    #pragma unroll
    for (int s = 0; s < 4; ++s) {
        #pragma unroll
        for (int o = 1; o <= 2; o <<= 1) {
            float vm = __shfl_xor_sync(0xffffffffu, maxv[s], o);
            int   im = __shfl_xor_sync(0xffffffffu, am[s],  o);
            if (vm > maxv[s] || (vm == maxv[s] && im < am[s])) { maxv[s] = vm; am[s] = im; }
            float vn = __shfl_xor_sync(0xffffffffu, minv[s], o);
            int   jn = __shfl_xor_sync(0xffffffffu, an[s],  o);
            if (vn < minv[s] || (vn == minv[s] && jn < an[s])) { minv[s] = vn; an[s] = jn; }
            esum[s] += __shfl_xor_sync(0xffffffffu, esum[s], o);
        }
    }

    // combine the two warp_n halves via smem, write per-split results
    __syncthreads();
    float* s_max = (float*)smem;
    int*   s_am  = (int*)(s_max + 128);
    float* s_min = (float*)(s_am + 128);
    int*   s_an  = (int*)(s_min + 128);
    float* s_es  = (float*)(s_an + 128);
    if (warp_n == 0 && tg == 0) {
        #pragma unroll
        for (int s = 0; s < 4; ++s) {
            int lr = warp_m * 32 + (s >> 1) * 16 + (s & 1) * 8 + g;
            s_max[lr] = maxv[s]; s_am[lr] = am[s];
            s_min[lr] = minv[s]; s_an[lr] = an[s];
            s_es[lr]  = esum[s];
        }
    }
    __syncthreads();
    if (warp_n == 1 && tg == 0) {
        #pragma unroll
        for (int s = 0; s < 4; ++s) {
            int lr = warp_m * 32 + (s >> 1) * 16 + (s & 1) * 8 + g;
            float vm = s_max[lr]; int im = s_am[lr];
            if (vm > maxv[s] || (vm == maxv[s] && im < am[s])) { maxv[s] = vm; am[s] = im; }
            float vn = s_min[lr]; int jn = s_an[lr];
            if (vn < minv[s] || (vn == minv[s] && jn < an[s])) { minv[s] = vn; an[s] = jn; }
            float es = esum[s] + s_es[lr];
            int grow = rowBase + lr;
            g_maxv[split][grow] = maxv[s]; g_am[split][grow] = am[s];
            g_minv[split][grow] = minv[s]; g_an[split][grow] = an[s];
            g_esum[split][grow] = es;
        }
    }
}

// ------------------------------------------------------------------
// 3) combine splits, margin, w-distances, per-row loss term
// ------------------------------------------------------------------
__global__ void finalize_kernel(const float* __restrict__ w) {
    const int row = blockIdx.x;
    float m = -2.0f, mn = 2.0f, E = 0.0f;
    int ms = 0, ls = 0;
    #pragma unroll
    for (int s = 0; s < NSPLIT; s++) {
        float v = g_maxv[s][row]; int iv = g_am[s][row];
        if (v > m || (v == m && iv < ms)) { m = v; ms = iv; }
        float u = g_minv[s][row]; int ju = g_an[s][row];
        if (u < mn || (u == mn && ju < ls)) { mn = u; ls = ju; }
        E += g_esum[s][row];
    }
    float margin = (1.0f - expf(mn - m)) * expf(m) / E;

    int t = threadIdx.x;
    float4 a = *(const float4*)&w[row * DD + t * 4];
    float4 b = *(const float4*)&w[ms  * DD + t * 4];
    float4 c = *(const float4*)&w[ls  * DD + t * 4];
    float dm = (a.x-b.x)*(a.x-b.x) + (a.y-b.y)*(a.y-b.y)
             + (a.z-b.z)*(a.z-b.z) + (a.w-b.w)*(a.w-b.w);
    float dl = (a.x-c.x)*(a.x-c.x) + (a.y-c.y)*(a.y-c.y)
             + (a.z-c.z)*(a.z-c.z) + (a.w-c.w)*(a.w-c.w);
    #pragma unroll
    for (int o = 16; o > 0; o >>= 1) {
        dm += __shfl_xor_sync(0xffffffffu, dm, o);
        dl += __shfl_xor_sync(0xffffffffu, dl, o);
    }
    __shared__ float sdm[4], sdl[4];
    int lane = t & 31, warp = t >> 5;
    if (lane == 0) { sdm[warp] = dm; sdl[warp] = dl; }
    __syncthreads();
    if (t == 0) {
        float DM = sdm[0] + sdm[1] + sdm[2] + sdm[3];
        float DL = sdl[0] + sdl[1] + sdl[2] + sdl[3];
        g_terms[row] = fmaxf(0.0f, sqrtf(DM) - sqrtf(DL) + margin);
    }
}

// ------------------------------------------------------------------
// 4) deterministic mean
// ------------------------------------------------------------------
__global__ void reduce_kernel(float* __restrict__ out) {
    __shared__ float sh[256];
    int t = threadIdx.x;
    float s = 0.0f;
    for (int i = t; i < CC; i += 256) s += g_terms[i];
    sh[t] = s;
    __syncthreads();
    for (int o = 128; o > 0; o >>= 1) {
        if (t < o) sh[t] += sh[t + o];
        __syncthreads();
    }
    if (t == 0) out[0] = sh[0] / (float)CC;
}

// ------------------------------------------------------------------
extern "C" void kernel_launch(void* const* d_in, const int* in_sizes, int n_in,
                              void* d_out, int out_size) {
    (void)in_sizes; (void)n_in; (void)out_size;
    const float* gt = (const float*)d_in[0];
    const float* w  = (const float*)d_in[1];
    float* out = (float*)d_out;

    cudaFuncSetAttribute(simstat_mma, cudaFuncAttributeMaxDynamicSharedMemorySize, SMEMB);

    transform_kernel<<<CC, 128>>>(gt);
    simstat_mma<<<dim3(CC / BM, NSPLIT), 256, SMEMB>>>();
    finalize_kernel<<<CC, 128>>>(w);
    reduce_kernel<<<1, 256>>>(out);
}

// round 10
// speedup vs baseline: 2.9291x; 1.1306x over previous
#include <cuda_runtime.h>
#include <cuda_bf16.h>
#include <cstdint>
#include <math.h>

#define CC 8192
#define DD 512
#define BM 128
#define BK 32
#define NCH (DD / BK)            // 16 k-chunks per tile
#define NTILE (CC / BM)          // 64 tiles per side

#define RSB 80                   // smem row stride bytes (64B data + 16B pad)
#define MATB (128 * RSB)         // 10240 B per matrix
#define STAGEB (4 * MATB)        // Ahi, Alo, Bhi, Blo
#define SMEMB (2 * STAGEB)       // 81920 B, double buffered
#define CSTRIDE 130              // fp32 C-stage row stride (floats)

// ---- scratch ----
__device__ __nv_bfloat16 g_hi[CC * DD];
__device__ __nv_bfloat16 g_lo[CC * DD];
__device__ float g_pmax[NTILE][CC];
__device__ int   g_pam[NTILE][CC];
__device__ float g_pmin[NTILE][CC];
__device__ int   g_pan[NTILE][CC];
__device__ float g_pes[NTILE][CC];
__device__ float g_terms[CC];

// ================= helpers =================
__device__ __forceinline__ uint32_t smem_to_u32(const void* p) {
    uint32_t a;
    asm("{ .reg .u64 t; cvta.to.shared.u64 t, %1; cvt.u32.u64 %0, t; }" : "=r"(a) : "l"(p));
    return a;
}
#define CP_ASYNC16(dst, src) \
    asm volatile("cp.async.cg.shared.global [%0], [%1], 16;" :: "r"(dst), "l"(src))
#define CP_COMMIT() asm volatile("cp.async.commit_group;" ::: "memory")
#define CP_WAIT1() asm volatile("cp.async.wait_group 1;" ::: "memory")
#define CP_WAIT0() asm volatile("cp.async.wait_group 0;" ::: "memory")

#define LDSM4(d, addr) \
    asm volatile("ldmatrix.sync.aligned.m8n8.x4.shared.b16 {%0,%1,%2,%3}, [%4];" \
        : "=r"((d)[0]), "=r"((d)[1]), "=r"((d)[2]), "=r"((d)[3]) : "r"(addr))

#define MMA_BF16(cr, a, b0, b1) \
    asm volatile("mma.sync.aligned.m16n8k16.row.col.f32.bf16.bf16.f32 " \
        "{%0,%1,%2,%3}, {%4,%5,%6,%7}, {%8,%9}, {%0,%1,%2,%3};" \
        : "+f"((cr)[0]), "+f"((cr)[1]), "+f"((cr)[2]), "+f"((cr)[3]) \
        : "r"((a)[0]), "r"((a)[1]), "r"((a)[2]), "r"((a)[3]), "r"(b0), "r"(b1))

// ------------------------------------------------------------------
// 1) normalize + bf16 hi/lo split, row-major
// ------------------------------------------------------------------
__global__ void transform_kernel(const float* __restrict__ x) {
    int row = blockIdx.x, t = threadIdx.x;
    float4 v = ((const float4*)(x + row * DD))[t];
    float s = v.x * v.x + v.y * v.y + v.z * v.z + v.w * v.w;
    #pragma unroll
    for (int o = 16; o > 0; o >>= 1) s += __shfl_xor_sync(0xffffffffu, s, o);
    __shared__ float sh[4];
    __shared__ float tot;
    int lane = t & 31, warp = t >> 5;
    if (lane == 0) sh[warp] = s;
    __syncthreads();
    if (t == 0) tot = sh[0] + sh[1] + sh[2] + sh[3];
    __syncthreads();
    float rn = rsqrtf(tot);
    float gv[4] = {v.x * rn, v.y * rn, v.z * rn, v.w * rn};
    __nv_bfloat16 hi[4], lo[4];
    #pragma unroll
    for (int i = 0; i < 4; i++) {
        hi[i] = __float2bfloat16(gv[i]);
        lo[i] = __float2bfloat16(gv[i] - __bfloat162float(hi[i]));
    }
    __nv_bfloat162* ph = (__nv_bfloat162*)g_hi + row * (DD / 2) + t * 2;
    __nv_bfloat162* pl = (__nv_bfloat162*)g_lo + row * (DD / 2) + t * 2;
    ph[0] = __halves2bfloat162(hi[0], hi[1]);
    ph[1] = __halves2bfloat162(hi[2], hi[3]);
    pl[0] = __halves2bfloat162(lo[0], lo[1]);
    pl[1] = __halves2bfloat162(lo[2], lo[3]);
}

// ------------------------------------------------------------------
// 2) symmetric bf16x3 mma.sync GEMM: one block per tile pair (I<=J).
//    Computes tile once; row-scan feeds rows I, col-scan feeds rows J.
// ------------------------------------------------------------------
__device__ __forceinline__ void prefetch_stage(uint32_t sb, int tid, int rowBase,
                                               int colBase, int chunk) {
    const uint32_t st = sb + (uint32_t)(chunk & 1) * STAGEB;
    const int kb = chunk * BK;
    #pragma unroll
    for (int i = 0; i < 2; ++i) {
        int e = tid + i * 256;          // 0..511
        int r = e >> 2, c4 = e & 3;
        uint32_t doff = (uint32_t)(r * RSB + c4 * 16);
        size_t aoff = (size_t)(rowBase + r) * DD + kb + c4 * 8;
        size_t boff = (size_t)(colBase + r) * DD + kb + c4 * 8;
        CP_ASYNC16(st + 0 * MATB + doff, g_hi + aoff);
        CP_ASYNC16(st + 1 * MATB + doff, g_lo + aoff);
        CP_ASYNC16(st + 2 * MATB + doff, g_hi + boff);
        CP_ASYNC16(st + 3 * MATB + doff, g_lo + boff);
    }
    CP_COMMIT();
}

__global__ void __launch_bounds__(256, 1) simstat_sym() {
    const int I = blockIdx.x, J = blockIdx.y;
    if (J < I) return;                 // upper triangle only

    extern __shared__ char smem[];
    const uint32_t sb = smem_to_u32(smem);
    const int tid = threadIdx.x;
    const int lane = tid & 31, wid = tid >> 5;
    const int warp_m = wid >> 1, warp_n = wid & 1;
    const int rowBase = I * BM, colBase = J * BM;
    const int g = lane >> 2, tg = lane & 3;

    // ldmatrix lane offsets (identical to the validated round-8 layout)
    const uint32_t aoffL = (uint32_t)((lane & 15) * RSB + ((lane >> 4) & 1) * 16)
                         + (uint32_t)(warp_m * 32 * RSB);
    const uint32_t boffL = (uint32_t)((((lane >> 4) & 1) * 8 + (lane & 7)) * RSB
                         + ((lane >> 3) & 1) * 16)
                         + (uint32_t)(warp_n * 64 * RSB);

    float c[2][8][4];
    #pragma unroll
    for (int mi = 0; mi < 2; ++mi)
        #pragma unroll
        for (int nj = 0; nj < 8; ++nj)
            #pragma unroll
            for (int q = 0; q < 4; ++q) c[mi][nj][q] = 0.0f;

    prefetch_stage(sb, tid, rowBase, colBase, 0);

    for (int chunk = 0; chunk < NCH; ++chunk) {
        __syncthreads();
        if (chunk + 1 < NCH) { prefetch_stage(sb, tid, rowBase, colBase, chunk + 1); CP_WAIT1(); }
        else CP_WAIT0();
        __syncthreads();

        const uint32_t st = sb + (uint32_t)(chunk & 1) * STAGEB;
        #pragma unroll
        for (int koi = 0; koi < 2; ++koi) {
            const uint32_t kob = (uint32_t)koi * 32;   // 16 bf16 = 32 B
            uint32_t ah[2][4], al[2][4];
            LDSM4(ah[0], st + 0 * MATB + aoffL + kob);
            LDSM4(ah[1], st + 0 * MATB + aoffL + 16 * RSB + kob);
            LDSM4(al[0], st + 1 * MATB + aoffL + kob);
            LDSM4(al[1], st + 1 * MATB + aoffL + 16 * RSB + kob);
            uint32_t bh[4][4], bl[4][4];
            #pragma unroll
            for (int njp = 0; njp < 4; ++njp) {
                LDSM4(bh[njp], st + 2 * MATB + boffL + (uint32_t)(njp * 16 * RSB) + kob);
                LDSM4(bl[njp], st + 3 * MATB + boffL + (uint32_t)(njp * 16 * RSB) + kob);
            }
            #pragma unroll
            for (int mi = 0; mi < 2; ++mi)
                #pragma unroll
                for (int nj = 0; nj < 8; ++nj) {
                    uint32_t h0 = bh[nj >> 1][(nj & 1) * 2];
                    uint32_t h1 = bh[nj >> 1][(nj & 1) * 2 + 1];
                    uint32_t l0 = bl[nj >> 1][(nj & 1) * 2];
                    uint32_t l1 = bl[nj >> 1][(nj & 1) * 2 + 1];
                    MMA_BF16(c[mi][nj], ah[mi], h0, h1);
                    MMA_BF16(c[mi][nj], ah[mi], l0, l1);
                    MMA_BF16(c[mi][nj], al[mi], h0, h1);
                }
        }
    }

    // ---- stage full fp32 C tile in smem (pipeline buffers are dead now) ----
    __syncthreads();
    float* cs = (float*)smem;
    #pragma unroll
    for (int mi = 0; mi < 2; ++mi)
        #pragma unroll
        for (int nj = 0; nj < 8; ++nj)
            #pragma unroll
            for (int q = 0; q < 4; ++q) {
                int rl = warp_m * 32 + mi * 16 + ((q >> 1) << 3) + g;
                int cl = warp_n * 64 + nj * 8 + tg * 2 + (q & 1);
                cs[rl * CSTRIDE + cl] = c[mi][nj][q];
            }
    __syncthreads();

    // ---- two scans: rows of I over cols J; rows of J over cols I ----
    if (tid < 128) {
        const int r = tid, grow = rowBase + r;
        float maxv = -2.0f, minv = 2.0f, esum = 0.0f;
        int am = 0, an = 0;
        #pragma unroll 4
        for (int cc = 0; cc < 128; ++cc) {
            int gcol = colBase + cc;
            float v = cs[r * CSTRIDE + cc];
            if (gcol != grow) {
                esum += __expf(v);
                if (v > maxv) { maxv = v; am = gcol; }
                if (v < minv) { minv = v; an = gcol; }
            }
        }
        g_pmax[J][grow] = maxv; g_pam[J][grow] = am;
        g_pmin[J][grow] = minv; g_pan[J][grow] = an;
        g_pes[J][grow]  = esum;
    } else if (I != J) {
        const int ccol = tid - 128, grow = colBase + ccol;
        float maxv = -2.0f, minv = 2.0f, esum = 0.0f;
        int am = 0, an = 0;
        #pragma unroll 4
        for (int r = 0; r < 128; ++r) {
            int gcol = rowBase + r;           // != grow since I != J
            float v = cs[r * CSTRIDE + ccol];
            esum += __expf(v);
            if (v > maxv) { maxv = v; am = gcol; }
            if (v < minv) { minv = v; an = gcol; }
        }
        g_pmax[I][grow] = maxv; g_pam[I][grow] = am;
        g_pmin[I][grow] = minv; g_pan[I][grow] = an;
        g_pes[I][grow]  = esum;
    }
}

// ------------------------------------------------------------------
// 3) merge 64 partials per row, margin, w-distances, per-row loss term
// ------------------------------------------------------------------
__global__ void finalize_kernel(const float* __restrict__ w) {
    const int row = blockIdx.x;
    const int t = threadIdx.x, lane = t & 31, warp = t >> 5;

    __shared__ float s_m[2], s_mn[2], s_E[2];
    __shared__ int   s_ms[2], s_ls[2];
    __shared__ float b_margin;
    __shared__ int   b_ms, b_ls;

    if (t < 64) {
        float m = g_pmax[t][row]; int ms = g_pam[t][row];
        float mn = g_pmin[t][row]; int ls = g_pan[t][row];
        float E = g_pes[t][row];
        #pragma unroll
        for (int o = 1; o < 32; o <<= 1) {
            float vm = __shfl_xor_sync(0xffffffffu, m, o);
            int   im = __shfl_xor_sync(0xffffffffu, ms, o);
            if (vm > m || (vm == m && im < ms)) { m = vm; ms = im; }
            float vn = __shfl_xor_sync(0xffffffffu, mn, o);
            int   jn = __shfl_xor_sync(0xffffffffu, ls, o);
            if (vn < mn || (vn == mn && jn < ls)) { mn = vn; ls = jn; }
            E += __shfl_xor_sync(0xffffffffu, E, o);
        }
        if (lane == 0) { s_m[warp] = m; s_ms[warp] = ms; s_mn[warp] = mn; s_ls[warp] = ls; s_E[warp] = E; }
    }
    __syncthreads();
    if (t == 0) {
        float m = s_m[0]; int ms = s_ms[0];
        if (s_m[1] > m || (s_m[1] == m && s_ms[1] < ms)) { m = s_m[1]; ms = s_ms[1]; }
        float mn = s_mn[0]; int ls = s_ls[0];
        if (s_mn[1] < mn || (s_mn[1] == mn && s_ls[1] < ls)) { mn = s_mn[1]; ls = s_ls[1]; }
        float E = s_E[0] + s_E[1];
        b_margin = (1.0f - expf(mn - m)) * expf(m) / E;
        b_ms = ms; b_ls = ls;
    }
    __syncthreads();

    const int ms = b_ms, ls = b_ls;
    float4 a = *(const float4*)&w[row * DD + t * 4];
    float4 b = *(const float4*)&w[ms  * DD + t * 4];
    float4 c = *(const float4*)&w[ls  * DD + t * 4];
    float dm = (a.x-b.x)*(a.x-b.x) + (a.y-b.y)*(a.y-b.y)
             + (a.z-b.z)*(a.z-b.z) + (a.w-b.w)*(a.w-b.w);
    float dl = (a.x-c.x)*(a.x-c.x) + (a.y-c.y)*(a.y-c.y)
             + (a.z-c.z)*(a.z-c.z) + (a.w-c.w)*(a.w-c.w);
    #pragma unroll
    for (int o = 16; o > 0; o >>= 1) {
        dm += __shfl_xor_sync(0xffffffffu, dm, o);
        dl += __shfl_xor_sync(0xffffffffu, dl, o);
    }
    __shared__ float sdm[4], sdl[4];
    if (lane == 0) { sdm[warp] = dm; sdl[warp] = dl; }
    __syncthreads();
    if (t == 0) {
        float DM = sdm[0] + sdm[1] + sdm[2] + sdm[3];
        float DL = sdl[0] + sdl[1] + sdl[2] + sdl[3];
        g_terms[row] = fmaxf(0.0f, sqrtf(DM) - sqrtf(DL) + b_margin);
    }
}

// ------------------------------------------------------------------
// 4) deterministic mean
// ------------------------------------------------------------------
__global__ void reduce_kernel(float* __restrict__ out) {
    __shared__ float sh[256];
    int t = threadIdx.x;
    float s = 0.0f;
    for (int i = t; i < CC; i += 256) s += g_terms[i];
    sh[t] = s;
    __syncthreads();
    for (int o = 128; o > 0; o >>= 1) {
        if (t < o) sh[t] += sh[t + o];
        __syncthreads();
    }
    if (t == 0) out[0] = sh[0] / (float)CC;
}

// ------------------------------------------------------------------
extern "C" void kernel_launch(void* const* d_in, const int* in_sizes, int n_in,
                              void* d_out, int out_size) {
    (void)in_sizes; (void)n_in; (void)out_size;
    const float* gt = (const float*)d_in[0];
    const float* w  = (const float*)d_in[1];
    float* out = (float*)d_out;

    cudaFuncSetAttribute(simstat_sym, cudaFuncAttributeMaxDynamicSharedMemorySize, SMEMB);

    transform_kernel<<<CC, 128>>>(gt);
    simstat_sym<<<dim3(NTILE, NTILE), 256, SMEMB>>>();
    finalize_kernel<<<CC, 128>>>(w);
    reduce_kernel<<<1, 256>>>(out);
}

// round 11
// speedup vs baseline: 2.9999x; 1.0242x over previous
#include <cuda_runtime.h>
#include <cuda_bf16.h>
#include <cstdint>
#include <math.h>

#define CC 8192
#define DD 512
#define BM 128
#define BK 32
#define NCH (DD / BK)            // 16 k-chunks per tile
#define NTILE (CC / BM)          // 64
#define NPAIRS (NTILE * (NTILE + 1) / 2)   // 2080
#define NBLK 152

#define RSB 80                   // smem row stride bytes
#define MATB (128 * RSB)         // 10240 B per matrix
#define STAGEB (4 * MATB)        // Ahi, Alo, Bhi, Blo
#define SMEMB (2 * STAGEB)       // 81920 B pipeline ring
#define CSTRIDE 129              // fp32 C-stage row stride (conflict-free both scans)
#define ESTAGEB (128 * CSTRIDE * 4)        // 66048
#define SCRB (1280 * 4)                    // merge scratch
#define SMEMTOT (SMEMB + ESTAGEB + SCRB)   // 153088

// ---- scratch ----
__device__ __nv_bfloat16 g_hi[CC * DD];
__device__ __nv_bfloat16 g_lo[CC * DD];
__device__ float g_pmax[NTILE][CC];
__device__ int   g_pam[NTILE][CC];
__device__ float g_pmin[NTILE][CC];
__device__ int   g_pan[NTILE][CC];
__device__ float g_pes[NTILE][CC];
__device__ float g_terms[CC];

// ================= helpers =================
__device__ __forceinline__ uint32_t smem_to_u32(const void* p) {
    uint32_t a;
    asm("{ .reg .u64 t; cvta.to.shared.u64 t, %1; cvt.u32.u64 %0, t; }" : "=r"(a) : "l"(p));
    return a;
}
#define CP_ASYNC16(dst, src) \
    asm volatile("cp.async.cg.shared.global [%0], [%1], 16;" :: "r"(dst), "l"(src))
#define CP_COMMIT() asm volatile("cp.async.commit_group;" ::: "memory")
#define CP_WAIT1() asm volatile("cp.async.wait_group 1;" ::: "memory")
#define CP_WAIT0() asm volatile("cp.async.wait_group 0;" ::: "memory")

#define LDSM4(d, addr) \
    asm volatile("ldmatrix.sync.aligned.m8n8.x4.shared.b16 {%0,%1,%2,%3}, [%4];" \
        : "=r"((d)[0]), "=r"((d)[1]), "=r"((d)[2]), "=r"((d)[3]) : "r"(addr))

#define MMA_BF16(cr, a, b0, b1) \
    asm volatile("mma.sync.aligned.m16n8k16.row.col.f32.bf16.bf16.f32 " \
        "{%0,%1,%2,%3}, {%4,%5,%6,%7}, {%8,%9}, {%0,%1,%2,%3};" \
        : "+f"((cr)[0]), "+f"((cr)[1]), "+f"((cr)[2]), "+f"((cr)[3]) \
        : "r"((a)[0]), "r"((a)[1]), "r"((a)[2]), "r"((a)[3]), "r"(b0), "r"(b1))

// ------------------------------------------------------------------
// 1) normalize + bf16 hi/lo split, row-major
// ------------------------------------------------------------------
__global__ void transform_kernel(const float* __restrict__ x) {
    int row = blockIdx.x, t = threadIdx.x;
    float4 v = ((const float4*)(x + row * DD))[t];
    float s = v.x * v.x + v.y * v.y + v.z * v.z + v.w * v.w;
    #pragma unroll
    for (int o = 16; o > 0; o >>= 1) s += __shfl_xor_sync(0xffffffffu, s, o);
    __shared__ float sh[4];
    __shared__ float tot;
    int lane = t & 31, warp = t >> 5;
    if (lane == 0) sh[warp] = s;
    __syncthreads();
    if (t == 0) tot = sh[0] + sh[1] + sh[2] + sh[3];
    __syncthreads();
    float rn = rsqrtf(tot);
    float gv[4] = {v.x * rn, v.y * rn, v.z * rn, v.w * rn};
    __nv_bfloat16 hi[4], lo[4];
    #pragma unroll
    for (int i = 0; i < 4; i++) {
        hi[i] = __float2bfloat16(gv[i]);
        lo[i] = __float2bfloat16(gv[i] - __bfloat162float(hi[i]));
    }
    __nv_bfloat162* ph = (__nv_bfloat162*)g_hi + row * (DD / 2) + t * 2;
    __nv_bfloat162* pl = (__nv_bfloat162*)g_lo + row * (DD / 2) + t * 2;
    ph[0] = __halves2bfloat162(hi[0], hi[1]);
    ph[1] = __halves2bfloat162(hi[2], hi[3]);
    pl[0] = __halves2bfloat162(lo[0], lo[1]);
    pl[1] = __halves2bfloat162(lo[2], lo[3]);
}

// ------------------------------------------------------------------
// 2) persistent symmetric bf16x3 GEMM; continuous pipeline across pairs
// ------------------------------------------------------------------
__device__ __forceinline__ void prefetch_stage(uint32_t sb, int tid, int rowBase,
                                               int colBase, int chunk, int slot) {
    const uint32_t st = sb + (uint32_t)slot * STAGEB;
    const int kb = chunk * BK;
    #pragma unroll
    for (int i = 0; i < 2; ++i) {
        int e = tid + i * 256;          // 0..511
        int r = e >> 2, c4 = e & 3;
        uint32_t doff = (uint32_t)(r * RSB + c4 * 16);
        size_t aoff = (size_t)(rowBase + r) * DD + kb + c4 * 8;
        size_t boff = (size_t)(colBase + r) * DD + kb + c4 * 8;
        CP_ASYNC16(st + 0 * MATB + doff, g_hi + aoff);
        CP_ASYNC16(st + 1 * MATB + doff, g_lo + aoff);
        CP_ASYNC16(st + 2 * MATB + doff, g_hi + boff);
        CP_ASYNC16(st + 3 * MATB + doff, g_lo + boff);
    }
    CP_COMMIT();
}

__global__ void __launch_bounds__(256, 1) simstat_persist() {
    extern __shared__ char smem[];
    const uint32_t sb = smem_to_u32(smem);
    float* cs  = (float*)(smem + SMEMB);
    float* scr = (float*)(smem + SMEMB + ESTAGEB);
    int*   scri = (int*)scr;
    const int tid = threadIdx.x;
    const int lane = tid & 31, wid = tid >> 5;
    const int warp_m = wid >> 1, warp_n = wid & 1;
    const int g = lane >> 2, tg = lane & 3;

    // contiguous pair span for this block
    const int b = blockIdx.x;
    const int start = b * 13 + (b < 104 ? b : 104);
    const int np = 13 + (b < 104 ? 1 : 0);
    int I = 0, rem = start;
    while (rem >= NTILE - I) { rem -= NTILE - I; I++; }
    int J = I + rem;
    int rowBase = I * BM, colBase = J * BM;

    const uint32_t aoffL = (uint32_t)((lane & 15) * RSB + ((lane >> 4) & 1) * 16)
                         + (uint32_t)(warp_m * 32 * RSB);
    const uint32_t boffL = (uint32_t)((((lane >> 4) & 1) * 8 + (lane & 7)) * RSB
                         + ((lane >> 3) & 1) * 16)
                         + (uint32_t)(warp_n * 64 * RSB);

    prefetch_stage(sb, tid, rowBase, colBase, 0, 0);
    int git = 0;

    for (int p = 0; p < np; ++p) {
        int nI = I, nJ = J + 1;
        if (nJ == NTILE) { nI = I + 1; nJ = nI; }
        const bool hasNext = (p + 1 < np);

        float c[2][8][4];
        #pragma unroll
        for (int mi = 0; mi < 2; ++mi)
            #pragma unroll
            for (int nj = 0; nj < 8; ++nj)
                #pragma unroll
                for (int q = 0; q < 4; ++q) c[mi][nj][q] = 0.0f;

        for (int chunk = 0; chunk < NCH; ++chunk, ++git) {
            __syncthreads();
            if (chunk < NCH - 1)
                prefetch_stage(sb, tid, rowBase, colBase, chunk + 1, (git + 1) & 1);
            else if (hasNext)
                prefetch_stage(sb, tid, nI * BM, nJ * BM, 0, (git + 1) & 1);
            if (chunk < NCH - 1 || hasNext) CP_WAIT1(); else CP_WAIT0();
            __syncthreads();

            const uint32_t st = sb + (uint32_t)(git & 1) * STAGEB;
            #pragma unroll
            for (int koi = 0; koi < 2; ++koi) {
                const uint32_t kob = (uint32_t)koi * 32;
                uint32_t ah[2][4], al[2][4];
                LDSM4(ah[0], st + 0 * MATB + aoffL + kob);
                LDSM4(ah[1], st + 0 * MATB + aoffL + 16 * RSB + kob);
                LDSM4(al[0], st + 1 * MATB + aoffL + kob);
                LDSM4(al[1], st + 1 * MATB + aoffL + 16 * RSB + kob);
                uint32_t bh[4][4], bl[4][4];
                #pragma unroll
                for (int njp = 0; njp < 4; ++njp) {
                    LDSM4(bh[njp], st + 2 * MATB + boffL + (uint32_t)(njp * 16 * RSB) + kob);
                    LDSM4(bl[njp], st + 3 * MATB + boffL + (uint32_t)(njp * 16 * RSB) + kob);
                }
                #pragma unroll
                for (int mi = 0; mi < 2; ++mi)
                    #pragma unroll
                    for (int nj = 0; nj < 8; ++nj) {
                        uint32_t h0 = bh[nj >> 1][(nj & 1) * 2];
                        uint32_t h1 = bh[nj >> 1][(nj & 1) * 2 + 1];
                        uint32_t l0 = bl[nj >> 1][(nj & 1) * 2];
                        uint32_t l1 = bl[nj >> 1][(nj & 1) * 2 + 1];
                        MMA_BF16(c[mi][nj], ah[mi], h0, h1);
                        MMA_BF16(c[mi][nj], ah[mi], l0, l1);
                        MMA_BF16(c[mi][nj], al[mi], h0, h1);
                    }
            }
        }

        // ---- epilogue (next pair's chunk 0 already in flight) ----
        __syncthreads();
        #pragma unroll
        for (int mi = 0; mi < 2; ++mi)
            #pragma unroll
            for (int nj = 0; nj < 8; ++nj)
                #pragma unroll
                for (int q = 0; q < 4; ++q) {
                    int rl = warp_m * 32 + mi * 16 + ((q >> 1) << 3) + g;
                    int cl = warp_n * 64 + nj * 8 + tg * 2 + (q & 1);
                    cs[rl * CSTRIDE + cl] = c[mi][nj][q];
                }
        __syncthreads();

        // row scan: 2 threads per row, 64 cols each (conflict-free)
        const int r = tid & 127, h = tid >> 7;
        const int grow = rowBase + r;
        float maxv = -2.0f, minv = 2.0f, esum = 0.0f;
        int am = 0, an = 0;
        {
            const int c0 = h * 64;
            #pragma unroll 4
            for (int cc = 0; cc < 64; ++cc) {
                int col = c0 + cc;
                int gcol = colBase + col;
                float v = cs[r * CSTRIDE + col];
                if (gcol != grow) {
                    esum += __expf(v);
                    if (v > maxv) { maxv = v; am = gcol; }
                    if (v < minv) { minv = v; an = gcol; }
                }
            }
        }
        // col scan: 2 threads per column, 64 rows each (conflict-free)
        float cmax = -2.0f, cmin = 2.0f, ces = 0.0f;
        int cam = 0, can = 0;
        if (I != J) {
            const int ccol = tid & 127;
            const int r0 = h * 64;
            #pragma unroll 4
            for (int rr = 0; rr < 64; ++rr) {
                int r2 = r0 + rr;
                float v = cs[r2 * CSTRIDE + ccol];
                int gi = rowBase + r2;
                ces += __expf(v);
                if (v > cmax) { cmax = v; cam = gi; }
                if (v < cmin) { cmin = v; can = gi; }
            }
        }
        if (tid >= 128) {
            int i = tid - 128;
            scr[i] = maxv; scri[128 + i] = am;
            scr[256 + i] = minv; scri[384 + i] = an;
            scr[512 + i] = esum;
            if (I != J) {
                scr[640 + i] = cmax; scri[768 + i] = cam;
                scr[896 + i] = cmin; scri[1024 + i] = can;
                scr[1152 + i] = ces;
            }
        }
        __syncthreads();
        if (tid < 128) {
            float o = scr[tid]; int oi = scri[128 + tid];
            if (o > maxv) { maxv = o; am = oi; }        // ties keep lower cols (h=0)
            o = scr[256 + tid]; oi = scri[384 + tid];
            if (o < minv) { minv = o; an = oi; }
            esum += scr[512 + tid];
            g_pmax[J][grow] = maxv; g_pam[J][grow] = am;
            g_pmin[J][grow] = minv; g_pan[J][grow] = an;
            g_pes[J][grow]  = esum;
            if (I != J) {
                const int gcl = colBase + tid;
                o = scr[640 + tid]; oi = scri[768 + tid];
                if (o > cmax) { cmax = o; cam = oi; }
                o = scr[896 + tid]; oi = scri[1024 + tid];
                if (o < cmin) { cmin = o; can = oi; }
                ces += scr[1152 + tid];
                g_pmax[I][gcl] = cmax; g_pam[I][gcl] = cam;
                g_pmin[I][gcl] = cmin; g_pan[I][gcl] = can;
                g_pes[I][gcl]  = ces;
            }
        }
        I = nI; J = nJ; rowBase = I * BM; colBase = J * BM;
    }
}

// ------------------------------------------------------------------
// 3) merge 64 partials per row, margin, w-distances, per-row loss term
// ------------------------------------------------------------------
__global__ void finalize_kernel(const float* __restrict__ w) {
    const int row = blockIdx.x;
    const int t = threadIdx.x, lane = t & 31, warp = t >> 5;

    __shared__ float s_m[2], s_mn[2], s_E[2];
    __shared__ int   s_ms[2], s_ls[2];
    __shared__ float b_margin;
    __shared__ int   b_ms, b_ls;

    if (t < 64) {
        float m = g_pmax[t][row]; int ms = g_pam[t][row];
        float mn = g_pmin[t][row]; int ls = g_pan[t][row];
        float E = g_pes[t][row];
        #pragma unroll
        for (int o = 1; o < 32; o <<= 1) {
            float vm = __shfl_xor_sync(0xffffffffu, m, o);
            int   im = __shfl_xor_sync(0xffffffffu, ms, o);
            if (vm > m || (vm == m && im < ms)) { m = vm; ms = im; }
            float vn = __shfl_xor_sync(0xffffffffu, mn, o);
            int   jn = __shfl_xor_sync(0xffffffffu, ls, o);
            if (vn < mn || (vn == mn && jn < ls)) { mn = vn; ls = jn; }
            E += __shfl_xor_sync(0xffffffffu, E, o);
        }
        if (lane == 0) { s_m[warp] = m; s_ms[warp] = ms; s_mn[warp] = mn; s_ls[warp] = ls; s_E[warp] = E; }
    }
    __syncthreads();
    if (t == 0) {
        float m = s_m[0]; int ms = s_ms[0];
        if (s_m[1] > m || (s_m[1] == m && s_ms[1] < ms)) { m = s_m[1]; ms = s_ms[1]; }
        float mn = s_mn[0]; int ls = s_ls[0];
        if (s_mn[1] < mn || (s_mn[1] == mn && s_ls[1] < ls)) { mn = s_mn[1]; ls = s_ls[1]; }
        float E = s_E[0] + s_E[1];
        b_margin = (expf(m) - expf(mn)) / E;
        b_ms = ms; b_ls = ls;
    }
    __syncthreads();

    const int ms = b_ms, ls = b_ls;
    float4 a = *(const float4*)&w[row * DD + t * 4];
    float4 b = *(const float4*)&w[ms  * DD + t * 4];
    float4 c = *(const float4*)&w[ls  * DD + t * 4];
    float dm = (a.x-b.x)*(a.x-b.x) + (a.y-b.y)*(a.y-b.y)
             + (a.z-b.z)*(a.z-b.z) + (a.w-b.w)*(a.w-b.w);
    float dl = (a.x-c.x)*(a.x-c.x) + (a.y-c.y)*(a.y-c.y)
             + (a.z-c.z)*(a.z-c.z) + (a.w-c.w)*(a.w-c.w);
    #pragma unroll
    for (int o = 16; o > 0; o >>= 1) {
        dm += __shfl_xor_sync(0xffffffffu, dm, o);
        dl += __shfl_xor_sync(0xffffffffu, dl, o);
    }
    __shared__ float sdm[4], sdl[4];
    if (lane == 0) { sdm[warp] = dm; sdl[warp] = dl; }
    __syncthreads();
    if (t == 0) {
        float DM = sdm[0] + sdm[1] + sdm[2] + sdm[3];
        float DL = sdl[0] + sdl[1] + sdl[2] + sdl[3];
        g_terms[row] = fmaxf(0.0f, sqrtf(DM) - sqrtf(DL) + b_margin);
    }
}

// ------------------------------------------------------------------
// 4) deterministic mean
// ------------------------------------------------------------------
__global__ void reduce_kernel(float* __restrict__ out) {
    __shared__ float sh[256];
    int t = threadIdx.x;
    float s = 0.0f;
    for (int i = t; i < CC; i += 256) s += g_terms[i];
    sh[t] = s;
    __syncthreads();
    for (int o = 128; o > 0; o >>= 1) {
        if (t < o) sh[t] += sh[t + o];
        __syncthreads();
    }
    if (t == 0) out[0] = sh[0] / (float)CC;
}

// ------------------------------------------------------------------
extern "C" void kernel_launch(void* const* d_in, const int* in_sizes, int n_in,
                              void* d_out, int out_size) {
    (void)in_sizes; (void)n_in; (void)out_size;
    const float* gt = (const float*)d_in[0];
    const float* w  = (const float*)d_in[1];
    float* out = (float*)d_out;

    cudaFuncSetAttribute(simstat_persist, cudaFuncAttributeMaxDynamicSharedMemorySize, SMEMTOT);

    transform_kernel<<<CC, 128>>>(gt);
    simstat_persist<<<NBLK, 256, SMEMTOT>>>();
    finalize_kernel<<<CC, 128>>>(w);
    reduce_kernel<<<1, 256>>>(out);
}

// round 12
// speedup vs baseline: 4.8454x; 1.6152x over previous
#include <cuda_runtime.h>
#include <cuda_bf16.h>
#include <cstdint>
#include <math.h>

#define CC 8192
#define DD 512
#define BM 128
#define BK 32
#define NCH (DD / BK)            // 16 k-chunks per tile
#define NTILE (CC / BM)          // 64
#define NPAIRS (NTILE * (NTILE + 1) / 2)   // 2080
#define NBLK 152

#define RSB 80                   // smem row stride bytes
#define MATB (128 * RSB)         // 10240 B per matrix
#define STAGEB (4 * MATB)        // Ahi, Alo, Bhi, Blo
#define SMEMB (2 * STAGEB)       // 81920 B pipeline ring

#define CSTRIDE 129              // stats-kernel smem stride (conflict-free both scans)
#define BSM_TILE (128 * CSTRIDE * 4)       // 66048
#define BSM_SCR (1280 * 4)
#define BSMEM (BSM_TILE + BSM_SCR)         // 71168

// ---- scratch ----
__device__ __nv_bfloat16 g_hi[CC * DD];
__device__ __nv_bfloat16 g_lo[CC * DD];
__device__ float g_C[(size_t)NPAIRS * BM * BM];   // 136 MB raw C tiles
__device__ float g_pmax[NTILE][CC];
__device__ int   g_pam[NTILE][CC];
__device__ float g_pmin[NTILE][CC];
__device__ int   g_pan[NTILE][CC];
__device__ float g_pes[NTILE][CC];
__device__ float g_terms[CC];

// ================= helpers =================
__device__ __forceinline__ uint32_t smem_to_u32(const void* p) {
    uint32_t a;
    asm("{ .reg .u64 t; cvta.to.shared.u64 t, %1; cvt.u32.u64 %0, t; }" : "=r"(a) : "l"(p));
    return a;
}
#define CP_ASYNC16(dst, src) \
    asm volatile("cp.async.cg.shared.global [%0], [%1], 16;" :: "r"(dst), "l"(src))
#define CP_COMMIT() asm volatile("cp.async.commit_group;" ::: "memory")
#define CP_WAIT1() asm volatile("cp.async.wait_group 1;" ::: "memory")
#define CP_WAIT0() asm volatile("cp.async.wait_group 0;" ::: "memory")

#define LDSM4(d, addr) \
    asm volatile("ldmatrix.sync.aligned.m8n8.x4.shared.b16 {%0,%1,%2,%3}, [%4];" \
        : "=r"((d)[0]), "=r"((d)[1]), "=r"((d)[2]), "=r"((d)[3]) : "r"(addr))

#define MMA_BF16(cr, a, b0, b1) \
    asm volatile("mma.sync.aligned.m16n8k16.row.col.f32.bf16.bf16.f32 " \
        "{%0,%1,%2,%3}, {%4,%5,%6,%7}, {%8,%9}, {%0,%1,%2,%3};" \
        : "+f"((cr)[0]), "+f"((cr)[1]), "+f"((cr)[2]), "+f"((cr)[3]) \
        : "r"((a)[0]), "r"((a)[1]), "r"((a)[2]), "r"((a)[3]), "r"(b0), "r"(b1))

// ------------------------------------------------------------------
// 1) normalize + bf16 hi/lo split, row-major
// ------------------------------------------------------------------
__global__ void transform_kernel(const float* __restrict__ x) {
    int row = blockIdx.x, t = threadIdx.x;
    float4 v = ((const float4*)(x + row * DD))[t];
    float s = v.x * v.x + v.y * v.y + v.z * v.z + v.w * v.w;
    #pragma unroll
    for (int o = 16; o > 0; o >>= 1) s += __shfl_xor_sync(0xffffffffu, s, o);
    __shared__ float sh[4];
    __shared__ float tot;
    int lane = t & 31, warp = t >> 5;
    if (lane == 0) sh[warp] = s;
    __syncthreads();
    if (t == 0) tot = sh[0] + sh[1] + sh[2] + sh[3];
    __syncthreads();
    float rn = rsqrtf(tot);
    float gv[4] = {v.x * rn, v.y * rn, v.z * rn, v.w * rn};
    __nv_bfloat16 hi[4], lo[4];
    #pragma unroll
    for (int i = 0; i < 4; i++) {
        hi[i] = __float2bfloat16(gv[i]);
        lo[i] = __float2bfloat16(gv[i] - __bfloat162float(hi[i]));
    }
    __nv_bfloat162* ph = (__nv_bfloat162*)g_hi + row * (DD / 2) + t * 2;
    __nv_bfloat162* pl = (__nv_bfloat162*)g_lo + row * (DD / 2) + t * 2;
    ph[0] = __halves2bfloat162(hi[0], hi[1]);
    ph[1] = __halves2bfloat162(hi[2], hi[3]);
    pl[0] = __halves2bfloat162(lo[0], lo[1]);
    pl[1] = __halves2bfloat162(lo[2], lo[3]);
}

// ------------------------------------------------------------------
// 2a) LEAN persistent GEMM: upper-triangle pairs, dump C tiles to gmem
// ------------------------------------------------------------------
__device__ __forceinline__ void prefetch_stage(uint32_t sb, int tid, int rowBase,
                                               int colBase, int chunk, int slot) {
    const uint32_t st = sb + (uint32_t)slot * STAGEB;
    const int kb = chunk * BK;
    #pragma unroll
    for (int i = 0; i < 2; ++i) {
        int e = tid + i * 256;          // 0..511
        int r = e >> 2, c4 = e & 3;
        uint32_t doff = (uint32_t)(r * RSB + c4 * 16);
        size_t aoff = (size_t)(rowBase + r) * DD + kb + c4 * 8;
        size_t boff = (size_t)(colBase + r) * DD + kb + c4 * 8;
        CP_ASYNC16(st + 0 * MATB + doff, g_hi + aoff);
        CP_ASYNC16(st + 1 * MATB + doff, g_lo + aoff);
        CP_ASYNC16(st + 2 * MATB + doff, g_hi + boff);
        CP_ASYNC16(st + 3 * MATB + doff, g_lo + boff);
    }
    CP_COMMIT();
}

__global__ void __launch_bounds__(256, 1) gemm_persist() {
    extern __shared__ char smem[];
    const uint32_t sb = smem_to_u32(smem);
    const int tid = threadIdx.x;
    const int lane = tid & 31, wid = tid >> 5;
    const int warp_m = wid >> 1, warp_n = wid & 1;
    const int g = lane >> 2, tg = lane & 3;

    const int b = blockIdx.x;
    const int start = b * 13 + (b < 104 ? b : 104);
    const int np = 13 + (b < 104 ? 1 : 0);
    int I = 0, rem = start;
    while (rem >= NTILE - I) { rem -= NTILE - I; I++; }
    int J = I + rem;
    int rowBase = I * BM, colBase = J * BM;

    const uint32_t aoffL = (uint32_t)((lane & 15) * RSB + ((lane >> 4) & 1) * 16)
                         + (uint32_t)(warp_m * 32 * RSB);
    const uint32_t boffL = (uint32_t)((((lane >> 4) & 1) * 8 + (lane & 7)) * RSB
                         + ((lane >> 3) & 1) * 16)
                         + (uint32_t)(warp_n * 64 * RSB);

    prefetch_stage(sb, tid, rowBase, colBase, 0, 0);
    int git = 0;

    for (int p = 0; p < np; ++p) {
        int nI = I, nJ = J + 1;
        if (nJ == NTILE) { nI = I + 1; nJ = nI; }
        const bool hasNext = (p + 1 < np);

        float c[2][8][4];
        #pragma unroll
        for (int mi = 0; mi < 2; ++mi)
            #pragma unroll
            for (int nj = 0; nj < 8; ++nj)
                #pragma unroll
                for (int q = 0; q < 4; ++q) c[mi][nj][q] = 0.0f;

        for (int chunk = 0; chunk < NCH; ++chunk, ++git) {
            __syncthreads();
            if (chunk < NCH - 1)
                prefetch_stage(sb, tid, rowBase, colBase, chunk + 1, (git + 1) & 1);
            else if (hasNext)
                prefetch_stage(sb, tid, nI * BM, nJ * BM, 0, (git + 1) & 1);
            if (chunk < NCH - 1 || hasNext) CP_WAIT1(); else CP_WAIT0();
            __syncthreads();

            const uint32_t st = sb + (uint32_t)(git & 1) * STAGEB;
            #pragma unroll
            for (int koi = 0; koi < 2; ++koi) {
                const uint32_t kob = (uint32_t)koi * 32;
                uint32_t ah[2][4], al[2][4];
                LDSM4(ah[0], st + 0 * MATB + aoffL + kob);
                LDSM4(ah[1], st + 0 * MATB + aoffL + 16 * RSB + kob);
                LDSM4(al[0], st + 1 * MATB + aoffL + kob);
                LDSM4(al[1], st + 1 * MATB + aoffL + 16 * RSB + kob);
                uint32_t bh[4][4], bl[4][4];
                #pragma unroll
                for (int njp = 0; njp < 4; ++njp) {
                    LDSM4(bh[njp], st + 2 * MATB + boffL + (uint32_t)(njp * 16 * RSB) + kob);
                    LDSM4(bl[njp], st + 3 * MATB + boffL + (uint32_t)(njp * 16 * RSB) + kob);
                }
                #pragma unroll
                for (int mi = 0; mi < 2; ++mi)
                    #pragma unroll
                    for (int nj = 0; nj < 8; ++nj) {
                        uint32_t h0 = bh[nj >> 1][(nj & 1) * 2];
                        uint32_t h1 = bh[nj >> 1][(nj & 1) * 2 + 1];
                        uint32_t l0 = bl[nj >> 1][(nj & 1) * 2];
                        uint32_t l1 = bl[nj >> 1][(nj & 1) * 2 + 1];
                        MMA_BF16(c[mi][nj], ah[mi], h0, h1);
                        MMA_BF16(c[mi][nj], ah[mi], l0, l1);
                        MMA_BF16(c[mi][nj], al[mi], h0, h1);
                    }
            }
        }

        // trivial epilogue: dump C tile (overlaps next pair's in-flight loads)
        float* dst = g_C + (size_t)(start + p) * (BM * BM);
        #pragma unroll
        for (int mi = 0; mi < 2; ++mi) {
            const int rl0 = warp_m * 32 + mi * 16 + g;
            #pragma unroll
            for (int nj = 0; nj < 8; ++nj) {
                const int cl = warp_n * 64 + nj * 8 + tg * 2;
                *(float2*)&dst[rl0 * BM + cl]       = make_float2(c[mi][nj][0], c[mi][nj][1]);
                *(float2*)&dst[(rl0 + 8) * BM + cl] = make_float2(c[mi][nj][2], c[mi][nj][3]);
            }
        }
        I = nI; J = nJ; rowBase = I * BM; colBase = J * BM;
    }
}

// ------------------------------------------------------------------
// 2b) stats harvest: one block per pair; row scan + col scan
// ------------------------------------------------------------------
__global__ void __launch_bounds__(256) stats_kernel() {
    extern __shared__ char smem[];
    float* cs  = (float*)smem;
    float* scr = (float*)(smem + BSM_TILE);
    int*   scri = (int*)scr;
    const int tid = threadIdx.x;

    const int p = blockIdx.x;
    int I = 0, rem = p;
    while (rem >= NTILE - I) { rem -= NTILE - I; I++; }
    const int J = I + rem;
    const int rowBase = I * BM, colBase = J * BM;

    // stage tile: coalesced gmem float4 reads, scalar smem stores (stride 129)
    const float* src = g_C + (size_t)p * (BM * BM);
    #pragma unroll
    for (int i = 0; i < 16; ++i) {
        int idx = tid + i * 256;                 // float4 index 0..4095
        int r = idx >> 5, c4 = (idx & 31) << 2;
        float4 v = *(const float4*)&src[r * BM + c4];
        float* d = &cs[r * CSTRIDE + c4];
        d[0] = v.x; d[1] = v.y; d[2] = v.z; d[3] = v.w;
    }
    __syncthreads();

    // row scan: 2 threads per row, 64 cols each
    const int r = tid & 127, h = tid >> 7;
    const int grow = rowBase + r;
    float maxv = -2.0f, minv = 2.0f, esum = 0.0f;
    int am = 0, an = 0;
    {
        const int c0 = h * 64;
        #pragma unroll 4
        for (int cc = 0; cc < 64; ++cc) {
            int col = c0 + cc;
            int gcol = colBase + col;
            float v = cs[r * CSTRIDE + col];
            if (gcol != grow) {
                esum += __expf(v);
                if (v > maxv) { maxv = v; am = gcol; }
                if (v < minv) { minv = v; an = gcol; }
            }
        }
    }
    // col scan: 2 threads per column, 64 rows each
    float cmax = -2.0f, cmin = 2.0f, ces = 0.0f;
    int cam = 0, can = 0;
    if (I != J) {
        const int ccol = tid & 127;
        const int r0 = h * 64;
        #pragma unroll 4
        for (int rr = 0; rr < 64; ++rr) {
            int r2 = r0 + rr;
            float v = cs[r2 * CSTRIDE + ccol];
            int gi = rowBase + r2;
            ces += __expf(v);
            if (v > cmax) { cmax = v; cam = gi; }
            if (v < cmin) { cmin = v; can = gi; }
        }
    }
    __syncthreads();
    if (tid >= 128) {
        int i = tid - 128;
        scr[i] = maxv; scri[128 + i] = am;
        scr[256 + i] = minv; scri[384 + i] = an;
        scr[512 + i] = esum;
        if (I != J) {
            scr[640 + i] = cmax; scri[768 + i] = cam;
            scr[896 + i] = cmin; scri[1024 + i] = can;
            scr[1152 + i] = ces;
        }
    }
    __syncthreads();
    if (tid < 128) {
        float o = scr[tid]; int oi = scri[128 + tid];
        if (o > maxv) { maxv = o; am = oi; }          // ties keep lower cols (h=0)
        o = scr[256 + tid]; oi = scri[384 + tid];
        if (o < minv) { minv = o; an = oi; }
        esum += scr[512 + tid];
        g_pmax[J][grow] = maxv; g_pam[J][grow] = am;
        g_pmin[J][grow] = minv; g_pan[J][grow] = an;
        g_pes[J][grow]  = esum;
        if (I != J) {
            const int gcl = colBase + tid;
            o = scr[640 + tid]; oi = scri[768 + tid];
            if (o > cmax) { cmax = o; cam = oi; }
            o = scr[896 + tid]; oi = scri[1024 + tid];
            if (o < cmin) { cmin = o; can = oi; }
            ces += scr[1152 + tid];
            g_pmax[I][gcl] = cmax; g_pam[I][gcl] = cam;
            g_pmin[I][gcl] = cmin; g_pan[I][gcl] = can;
            g_pes[I][gcl]  = ces;
        }
    }
}

// ------------------------------------------------------------------
// 3) merge 64 partials per row, margin, w-distances, per-row loss term
// ------------------------------------------------------------------
__global__ void finalize_kernel(const float* __restrict__ w) {
    const int row = blockIdx.x;
    const int t = threadIdx.x, lane = t & 31, warp = t >> 5;

    __shared__ float s_m[2], s_mn[2], s_E[2];
    __shared__ int   s_ms[2], s_ls[2];
    __shared__ float b_margin;
    __shared__ int   b_ms, b_ls;

    if (t < 64) {
        float m = g_pmax[t][row]; int ms = g_pam[t][row];
        float mn = g_pmin[t][row]; int ls = g_pan[t][row];
        float E = g_pes[t][row];
        #pragma unroll
        for (int o = 1; o < 32; o <<= 1) {
            float vm = __shfl_xor_sync(0xffffffffu, m, o);
            int   im = __shfl_xor_sync(0xffffffffu, ms, o);
            if (vm > m || (vm == m && im < ms)) { m = vm; ms = im; }
            float vn = __shfl_xor_sync(0xffffffffu, mn, o);
            int   jn = __shfl_xor_sync(0xffffffffu, ls, o);
            if (vn < mn || (vn == mn && jn < ls)) { mn = vn; ls = jn; }
            E += __shfl_xor_sync(0xffffffffu, E, o);
        }
        if (lane == 0) { s_m[warp] = m; s_ms[warp] = ms; s_mn[warp] = mn; s_ls[warp] = ls; s_E[warp] = E; }
    }
    __syncthreads();
    if (t == 0) {
        float m = s_m[0]; int ms = s_ms[0];
        if (s_m[1] > m || (s_m[1] == m && s_ms[1] < ms)) { m = s_m[1]; ms = s_ms[1]; }
        float mn = s_mn[0]; int ls = s_ls[0];
        if (s_mn[1] < mn || (s_mn[1] == mn && s_ls[1] < ls)) { mn = s_mn[1]; ls = s_ls[1]; }
        float E = s_E[0] + s_E[1];
        b_margin = (expf(m) - expf(mn)) / E;
        b_ms = ms; b_ls = ls;
    }
    __syncthreads();

    const int ms = b_ms, ls = b_ls;
    float4 a = *(const float4*)&w[row * DD + t * 4];
    float4 b = *(const float4*)&w[ms  * DD + t * 4];
    float4 c = *(const float4*)&w[ls  * DD + t * 4];
    float dm = (a.x-b.x)*(a.x-b.x) + (a.y-b.y)*(a.y-b.y)
             + (a.z-b.z)*(a.z-b.z) + (a.w-b.w)*(a.w-b.w);
    float dl = (a.x-c.x)*(a.x-c.x) + (a.y-c.y)*(a.y-c.y)
             + (a.z-c.z)*(a.z-c.z) + (a.w-c.w)*(a.w-c.w);
    #pragma unroll
    for (int o = 16; o > 0; o >>= 1) {
        dm += __shfl_xor_sync(0xffffffffu, dm, o);
        dl += __shfl_xor_sync(0xffffffffu, dl, o);
    }
    __shared__ float sdm[4], sdl[4];
    if (lane == 0) { sdm[warp] = dm; sdl[warp] = dl; }
    __syncthreads();
    if (t == 0) {
        float DM = sdm[0] + sdm[1] + sdm[2] + sdm[3];
        float DL = sdl[0] + sdl[1] + sdl[2] + sdl[3];
        g_terms[row] = fmaxf(0.0f, sqrtf(DM) - sqrtf(DL) + b_margin);
    }
}

// ------------------------------------------------------------------
// 4) deterministic mean
// ------------------------------------------------------------------
__global__ void reduce_kernel(float* __restrict__ out) {
    __shared__ float sh[256];
    int t = threadIdx.x;
    float s = 0.0f;
    for (int i = t; i < CC; i += 256) s += g_terms[i];
    sh[t] = s;
    __syncthreads();
    for (int o = 128; o > 0; o >>= 1) {
        if (t < o) sh[t] += sh[t + o];
        __syncthreads();
    }
    if (t == 0) out[0] = sh[0] / (float)CC;
}

// ------------------------------------------------------------------
extern "C" void kernel_launch(void* const* d_in, const int* in_sizes, int n_in,
                              void* d_out, int out_size) {
    (void)in_sizes; (void)n_in; (void)out_size;
    const float* gt = (const float*)d_in[0];
    const float* w  = (const float*)d_in[1];
    float* out = (float*)d_out;

    cudaFuncSetAttribute(gemm_persist, cudaFuncAttributeMaxDynamicSharedMemorySize, SMEMB);
    cudaFuncSetAttribute(stats_kernel, cudaFuncAttributeMaxDynamicSharedMemorySize, BSMEM);

    transform_kernel<<<CC, 128>>>(gt);
    gemm_persist<<<NBLK, 256, SMEMB>>>();
    stats_kernel<<<NPAIRS, 256, BSMEM>>>();
    finalize_kernel<<<CC, 128>>>(w);
    reduce_kernel<<<1, 256>>>(out);
}

// round 14
// speedup vs baseline: 4.9472x; 1.0210x over previous
#include <cuda_runtime.h>
#include <cuda_bf16.h>
#include <cstdint>
#include <math.h>

#define CC 8192
#define DD 512
#define BM 128
#define BK 32
#define NCH (DD / BK)            // 16 k-chunks per tile
#define NTILE (CC / BM)          // 64
#define NPAIRS (NTILE * (NTILE + 1) / 2)   // 2080
#define NBLK 152

#define RSB 80                   // smem row stride bytes
#define MATB (128 * RSB)         // 10240 B per matrix
#define STAGEB (4 * MATB)        // Ahi, Alo, Bhi, Blo
#define SMEMB (2 * STAGEB)       // 81920 B pipeline ring

#define CSTRIDE 129              // stats-kernel smem stride (conflict-free both scans)
#define BSMEM (128 * CSTRIDE * 4)          // 66048 (scratch reuses this region)

// ---- scratch ----
__device__ __nv_bfloat16 g_hi[CC * DD];
__device__ __nv_bfloat16 g_lo[CC * DD];
__device__ float g_C[(size_t)NPAIRS * BM * BM];   // 136 MB raw C tiles
__device__ float g_pmax[NTILE][CC];
__device__ int   g_pam[NTILE][CC];
__device__ float g_pmin[NTILE][CC];
__device__ int   g_pan[NTILE][CC];
__device__ float g_pes[NTILE][CC];
__device__ float g_terms[CC];

// ================= helpers =================
__device__ __forceinline__ uint32_t smem_to_u32(const void* p) {
    uint32_t a;
    asm("{ .reg .u64 t; cvta.to.shared.u64 t, %1; cvt.u32.u64 %0, t; }" : "=r"(a) : "l"(p));
    return a;
}
#define CP_ASYNC16(dst, src) \
    asm volatile("cp.async.cg.shared.global [%0], [%1], 16;" :: "r"(dst), "l"(src))
#define CP_COMMIT() asm volatile("cp.async.commit_group;" ::: "memory")
#define CP_WAIT1() asm volatile("cp.async.wait_group 1;" ::: "memory")
#define CP_WAIT0() asm volatile("cp.async.wait_group 0;" ::: "memory")

#define LDSM4(d, addr) \
    asm volatile("ldmatrix.sync.aligned.m8n8.x4.shared.b16 {%0,%1,%2,%3}, [%4];" \
        : "=r"((d)[0]), "=r"((d)[1]), "=r"((d)[2]), "=r"((d)[3]) : "r"(addr))

#define MMA_BF16(cr, a, b0, b1) \
    asm volatile("mma.sync.aligned.m16n8k16.row.col.f32.bf16.bf16.f32 " \
        "{%0,%1,%2,%3}, {%4,%5,%6,%7}, {%8,%9}, {%0,%1,%2,%3};" \
        : "+f"((cr)[0]), "+f"((cr)[1]), "+f"((cr)[2]), "+f"((cr)[3]) \
        : "r"((a)[0]), "r"((a)[1]), "r"((a)[2]), "r"((a)[3]), "r"(b0), "r"(b1))

// ------------------------------------------------------------------
// 1) normalize + bf16 hi/lo split, row-major
// ------------------------------------------------------------------
__global__ void transform_kernel(const float* __restrict__ x) {
    int row = blockIdx.x, t = threadIdx.x;
    float4 v = ((const float4*)(x + row * DD))[t];
    float s = v.x * v.x + v.y * v.y + v.z * v.z + v.w * v.w;
    #pragma unroll
    for (int o = 16; o > 0; o >>= 1) s += __shfl_xor_sync(0xffffffffu, s, o);
    __shared__ float sh[4];
    __shared__ float tot;
    int lane = t & 31, warp = t >> 5;
    if (lane == 0) sh[warp] = s;
    __syncthreads();
    if (t == 0) tot = sh[0] + sh[1] + sh[2] + sh[3];
    __syncthreads();
    float rn = rsqrtf(tot);
    float gv[4] = {v.x * rn, v.y * rn, v.z * rn, v.w * rn};
    __nv_bfloat16 hi[4], lo[4];
    #pragma unroll
    for (int i = 0; i < 4; i++) {
        hi[i] = __float2bfloat16(gv[i]);
        lo[i] = __float2bfloat16(gv[i] - __bfloat162float(hi[i]));
    }
    __nv_bfloat162* ph = (__nv_bfloat162*)g_hi + row * (DD / 2) + t * 2;
    __nv_bfloat162* pl = (__nv_bfloat162*)g_lo + row * (DD / 2) + t * 2;
    ph[0] = __halves2bfloat162(hi[0], hi[1]);
    ph[1] = __halves2bfloat162(hi[2], hi[3]);
    pl[0] = __halves2bfloat162(lo[0], lo[1]);
    pl[1] = __halves2bfloat162(lo[2], lo[3]);
}

// ------------------------------------------------------------------
// 2a) LEAN persistent GEMM: upper-triangle pairs, dump C tiles to gmem
// ------------------------------------------------------------------
__device__ __forceinline__ void prefetch_stage(uint32_t sb, int tid, int rowBase,
                                               int colBase, int chunk, int slot) {
    const uint32_t st = sb + (uint32_t)slot * STAGEB;
    const int kb = chunk * BK;
    #pragma unroll
    for (int i = 0; i < 2; ++i) {
        int e = tid + i * 256;          // 0..511
        int r = e >> 2, c4 = e & 3;
        uint32_t doff = (uint32_t)(r * RSB + c4 * 16);
        size_t aoff = (size_t)(rowBase + r) * DD + kb + c4 * 8;
        size_t boff = (size_t)(colBase + r) * DD + kb + c4 * 8;
        CP_ASYNC16(st + 0 * MATB + doff, g_hi + aoff);
        CP_ASYNC16(st + 1 * MATB + doff, g_lo + aoff);
        CP_ASYNC16(st + 2 * MATB + doff, g_hi + boff);
        CP_ASYNC16(st + 3 * MATB + doff, g_lo + boff);
    }
    CP_COMMIT();
}

__global__ void __launch_bounds__(256, 1) gemm_persist() {
    extern __shared__ char smem[];
    const uint32_t sb = smem_to_u32(smem);
    const int tid = threadIdx.x;
    const int lane = tid & 31, wid = tid >> 5;
    const int warp_m = wid >> 1, warp_n = wid & 1;
    const int g = lane >> 2, tg = lane & 3;

    const int b = blockIdx.x;
    const int start = b * 13 + (b < 104 ? b : 104);
    const int np = 13 + (b < 104 ? 1 : 0);
    int I = 0, rem = start;
    while (rem >= NTILE - I) { rem -= NTILE - I; I++; }
    int J = I + rem;
    int rowBase = I * BM, colBase = J * BM;

    const uint32_t aoffL = (uint32_t)((lane & 15) * RSB + ((lane >> 4) & 1) * 16)
                         + (uint32_t)(warp_m * 32 * RSB);
    const uint32_t boffL = (uint32_t)((((lane >> 4) & 1) * 8 + (lane & 7)) * RSB
                         + ((lane >> 3) & 1) * 16)
                         + (uint32_t)(warp_n * 64 * RSB);

    prefetch_stage(sb, tid, rowBase, colBase, 0, 0);
    int git = 0;

    for (int p = 0; p < np; ++p) {
        int nI = I, nJ = J + 1;
        if (nJ == NTILE) { nI = I + 1; nJ = nI; }
        const bool hasNext = (p + 1 < np);

        float c[2][8][4];
        #pragma unroll
        for (int mi = 0; mi < 2; ++mi)
            #pragma unroll
            for (int nj = 0; nj < 8; ++nj)
                #pragma unroll
                for (int q = 0; q < 4; ++q) c[mi][nj][q] = 0.0f;

        for (int chunk = 0; chunk < NCH; ++chunk, ++git) {
            __syncthreads();
            if (chunk < NCH - 1)
                prefetch_stage(sb, tid, rowBase, colBase, chunk + 1, (git + 1) & 1);
            else if (hasNext)
                prefetch_stage(sb, tid, nI * BM, nJ * BM, 0, (git + 1) & 1);
            if (chunk < NCH - 1 || hasNext) CP_WAIT1(); else CP_WAIT0();
            __syncthreads();

            const uint32_t st = sb + (uint32_t)(git & 1) * STAGEB;
            #pragma unroll
            for (int koi = 0; koi < 2; ++koi) {
                const uint32_t kob = (uint32_t)koi * 32;
                uint32_t ah[2][4], al[2][4];
                LDSM4(ah[0], st + 0 * MATB + aoffL + kob);
                LDSM4(ah[1], st + 0 * MATB + aoffL + 16 * RSB + kob);
                LDSM4(al[0], st + 1 * MATB + aoffL + kob);
                LDSM4(al[1], st + 1 * MATB + aoffL + 16 * RSB + kob);
                uint32_t bh[4][4], bl[4][4];
                #pragma unroll
                for (int njp = 0; njp < 4; ++njp) {
                    LDSM4(bh[njp], st + 2 * MATB + boffL + (uint32_t)(njp * 16 * RSB) + kob);
                    LDSM4(bl[njp], st + 3 * MATB + boffL + (uint32_t)(njp * 16 * RSB) + kob);
                }
                #pragma unroll
                for (int mi = 0; mi < 2; ++mi)
                    #pragma unroll
                    for (int nj = 0; nj < 8; ++nj) {
                        uint32_t h0 = bh[nj >> 1][(nj & 1) * 2];
                        uint32_t h1 = bh[nj >> 1][(nj & 1) * 2 + 1];
                        uint32_t l0 = bl[nj >> 1][(nj & 1) * 2];
                        uint32_t l1 = bl[nj >> 1][(nj & 1) * 2 + 1];
                        MMA_BF16(c[mi][nj], ah[mi], h0, h1);
                        MMA_BF16(c[mi][nj], ah[mi], l0, l1);
                        MMA_BF16(c[mi][nj], al[mi], h0, h1);
                    }
            }
        }

        // trivial epilogue: dump C tile (overlaps next pair's in-flight loads)
        float* dst = g_C + (size_t)(start + p) * (BM * BM);
        #pragma unroll
        for (int mi = 0; mi < 2; ++mi) {
            const int rl0 = warp_m * 32 + mi * 16 + g;
            #pragma unroll
            for (int nj = 0; nj < 8; ++nj) {
                const int cl = warp_n * 64 + nj * 8 + tg * 2;
                *(float2*)&dst[rl0 * BM + cl]       = make_float2(c[mi][nj][0], c[mi][nj][1]);
                *(float2*)&dst[(rl0 + 8) * BM + cl] = make_float2(c[mi][nj][2], c[mi][nj][3]);
            }
        }
        I = nI; J = nJ; rowBase = I * BM; colBase = J * BM;
    }
}

// ------------------------------------------------------------------
// 2b) stats harvest: 512 threads/pair; row scan on S writes exp in place,
//     col scan consumes exp values (monotone => same arg indices)
// ------------------------------------------------------------------
__global__ void __launch_bounds__(512) stats_kernel() {
    extern __shared__ char smem[];
    float* cs = (float*)smem;
    const int tid = threadIdx.x;

    const int p = blockIdx.x;
    int I = 0, rem = p;
    while (rem >= NTILE - I) { rem -= NTILE - I; I++; }
    const int J = I + rem;
    const int rowBase = I * BM, colBase = J * BM;

    // stage tile: coalesced float4 reads, stride-129 smem
    const float* src = g_C + (size_t)p * (BM * BM);
    #pragma unroll
    for (int i = 0; i < 8; ++i) {
        int idx = tid + i * 512;                 // float4 index 0..4095
        int r = idx >> 5, c4 = (idx & 31) << 2;
        float4 v = *(const float4*)&src[r * BM + c4];
        float* d = &cs[r * CSTRIDE + c4];
        d[0] = v.x; d[1] = v.y; d[2] = v.z; d[3] = v.w;
    }
    __syncthreads();

    // row scan: 4 threads per row, 32 cols each; write exp back in place
    const int r = tid & 127, h = tid >> 7;       // h = 0..3
    const int grow = rowBase + r;
    float maxv = -2.0f, minv = 2.0f, esum = 0.0f;
    int am = 0, an = 0;
    {
        const int c0 = h * 32;
        #pragma unroll 4
        for (int cc = 0; cc < 32; ++cc) {
            int col = c0 + cc;
            int gcol = colBase + col;
            float v = cs[r * CSTRIDE + col];
            float e = __expf(v);
            cs[r * CSTRIDE + col] = e;
            if (gcol != grow) {
                esum += e;
                if (v > maxv) { maxv = v; am = gcol; }
                if (v < minv) { minv = v; an = gcol; }
            }
        }
    }
    __syncthreads();                             // all exp values in place

    // col scan on exp values: 4 threads per column, 32 rows each
    float cmax = 0.0f, cmin = 3.0f, ces = 0.0f;  // exp(S) in [e^-1, e^1]
    int cam = 0, can = 0;
    if (I != J) {
        const int ccol = r;
        const int r0 = h * 32;
        #pragma unroll 4
        for (int rr = 0; rr < 32; ++rr) {
            int r2 = r0 + rr;
            float e = cs[r2 * CSTRIDE + ccol];
            int gi = rowBase + r2;
            ces += e;
            if (e > cmax) { cmax = e; cam = gi; }
            if (e < cmin) { cmin = e; can = gi; }
        }
    }
    __syncthreads();                             // all cs reads done; reuse as scratch

    float* scr = cs;
    int*   scri = (int*)cs;
    if (h > 0) {
        int bo = (h - 1) * 128 + r;
        scr[bo] = maxv;          scri[384 + bo]  = am;
        scr[768 + bo] = minv;    scri[1152 + bo] = an;
        scr[1536 + bo] = esum;
        if (I != J) {
            scr[1920 + bo] = cmax;  scri[2304 + bo] = cam;
            scr[2688 + bo] = cmin;  scri[3072 + bo] = can;
            scr[3456 + bo] = ces;
        }
    }
    __syncthreads();
    if (h == 0) {
        #pragma unroll
        for (int k = 0; k < 3; ++k) {           // ascending h keeps lowest index on ties
            int bo = k * 128 + r;
            float o = scr[bo]; int oi = scri[384 + bo];
            if (o > maxv) { maxv = o; am = oi; }
            o = scr[768 + bo]; oi = scri[1152 + bo];
            if (o < minv) { minv = o; an = oi; }
            esum += scr[1536 + bo];
        }
        g_pmax[J][grow] = maxv; g_pam[J][grow] = am;
        g_pmin[J][grow] = minv; g_pan[J][grow] = an;
        g_pes[J][grow]  = esum;
        if (I != J) {
            #pragma unroll
            for (int k = 0; k < 3; ++k) {
                int bo = k * 128 + r;
                float o = scr[1920 + bo]; int oi = scri[2304 + bo];
                if (o > cmax) { cmax = o; cam = oi; }
                o = scr[2688 + bo]; oi = scri[3072 + bo];
                if (o < cmin) { cmin = o; can = oi; }
                ces += scr[3456 + bo];
            }
            const int gcl = colBase + r;
            g_pmax[I][gcl] = cmax; g_pam[I][gcl] = cam;
            g_pmin[I][gcl] = cmin; g_pan[I][gcl] = can;
            g_pes[I][gcl]  = ces;
        }
    }
}

// ------------------------------------------------------------------
// 3) merge 64 partials per row, margin, w-distances, per-row loss term
//    NOTE: col-scan partials store exp-space max/min; row-scan partials store
//    S-space. Merge must be space-consistent -> normalize to exp-space here.
// ------------------------------------------------------------------
__global__ void finalize_kernel(const float* __restrict__ w) {
    const int row = blockIdx.x;
    const int t = threadIdx.x, lane = t & 31, warp = t >> 5;
    const int tileRow = row >> 7;               // this row's own tile index

    __shared__ float s_m[2], s_mn[2], s_E[2];
    __shared__ int   s_ms[2], s_ls[2];
    __shared__ float b_margin;
    __shared__ int   b_ms, b_ls;

    if (t < 64) {
        // partial from tile t: row-scan (S-space) if t >= tileRow... distinguish:
        // g_p*[J][row] written by row-scan (S-space) when J >= tileRow;
        // g_p*[I][row] written by col-scan (exp-space) when I < tileRow.
        float rawm = g_pmax[t][row];
        float rawn = g_pmin[t][row];
        float m, mn;
        if (t >= tileRow) { m = __expf(rawm); mn = __expf(rawn); }  // S -> exp space
        else              { m = rawm;        mn = rawn;          }   // already exp
        int ms = g_pam[t][row];
        int ls = g_pan[t][row];
        float E = g_pes[t][row];
        #pragma unroll
        for (int o = 1; o < 32; o <<= 1) {
            float vm = __shfl_xor_sync(0xffffffffu, m, o);
            int   im = __shfl_xor_sync(0xffffffffu, ms, o);
            if (vm > m || (vm == m && im < ms)) { m = vm; ms = im; }
            float vn = __shfl_xor_sync(0xffffffffu, mn, o);
            int   jn = __shfl_xor_sync(0xffffffffu, ls, o);
            if (vn < mn || (vn == mn && jn < ls)) { mn = vn; ls = jn; }
            E += __shfl_xor_sync(0xffffffffu, E, o);
        }
        if (lane == 0) { s_m[warp] = m; s_ms[warp] = ms; s_mn[warp] = mn; s_ls[warp] = ls; s_E[warp] = E; }
    }
    __syncthreads();
    if (t == 0) {
        float m = s_m[0]; int ms = s_ms[0];
        if (s_m[1] > m || (s_m[1] == m && s_ms[1] < ms)) { m = s_m[1]; ms = s_ms[1]; }
        float mn = s_mn[0]; int ls = s_ls[0];
        if (s_mn[1] < mn || (s_mn[1] == mn && s_ls[1] < ls)) { mn = s_mn[1]; ls = s_ls[1]; }
        float E = s_E[0] + s_E[1];
        b_margin = (m - mn) / E;                // m, mn already exp-space
        b_ms = ms; b_ls = ls;
    }
    __syncthreads();

    const int ms = b_ms, ls = b_ls;
    float4 a = *(const float4*)&w[row * DD + t * 4];
    float4 b = *(const float4*)&w[ms  * DD + t * 4];
    float4 c = *(const float4*)&w[ls  * DD + t * 4];
    float dm = (a.x-b.x)*(a.x-b.x) + (a.y-b.y)*(a.y-b.y)
             + (a.z-b.z)*(a.z-b.z) + (a.w-b.w)*(a.w-b.w);
    float dl = (a.x-c.x)*(a.x-c.x) + (a.y-c.y)*(a.y-c.y)
             + (a.z-c.z)*(a.z-c.z) + (a.w-c.w)*(a.w-c.w);
    #pragma unroll
    for (int o = 16; o > 0; o >>= 1) {
        dm += __shfl_xor_sync(0xffffffffu, dm, o);
        dl += __shfl_xor_sync(0xffffffffu, dl, o);
    }
    __shared__ float sdm[4], sdl[4];
    if (lane == 0) { sdm[warp] = dm; sdl[warp] = dl; }
    __syncthreads();
    if (t == 0) {
        float DM = sdm[0] + sdm[1] + sdm[2] + sdm[3];
        float DL = sdl[0] + sdl[1] + sdl[2] + sdl[3];
        g_terms[row] = fmaxf(0.0f, sqrtf(DM) - sqrtf(DL) + b_margin);
    }
}

// ------------------------------------------------------------------
// 4) deterministic mean (1024 threads)
// ------------------------------------------------------------------
__global__ void reduce_kernel(float* __restrict__ out) {
    __shared__ float sh[1024];
    int t = threadIdx.x;
    float s = 0.0f;
    for (int i = t; i < CC; i += 1024) s += g_terms[i];
    sh[t] = s;
    __syncthreads();
    for (int o = 512; o > 0; o >>= 1) {
        if (t < o) sh[t] += sh[t + o];
        __syncthreads();
    }
    if (t == 0) out[0] = sh[0] / (float)CC;
}

// ------------------------------------------------------------------
extern "C" void kernel_launch(void* const* d_in, const int* in_sizes, int n_in,
                              void* d_out, int out_size) {
    (void)in_sizes; (void)n_in; (void)out_size;
    const float* gt = (const float*)d_in[0];
    const float* w  = (const float*)d_in[1];
    float* out = (float*)d_out;

    cudaFuncSetAttribute(gemm_persist, cudaFuncAttributeMaxDynamicSharedMemorySize, SMEMB);
    cudaFuncSetAttribute(stats_kernel, cudaFuncAttributeMaxDynamicSharedMemorySize, BSMEM);

    transform_kernel<<<CC, 128>>>(gt);
    gemm_persist<<<NBLK, 256, SMEMB>>>();
    stats_kernel<<<NPAIRS, 512, BSMEM>>>();
    finalize_kernel<<<CC, 128>>>(w);
    reduce_kernel<<<1, 1024>>>(out);
}